// round 3
// baseline (speedup 1.0000x reference)
#include <cuda_runtime.h>
#include <cstdint>
#include <cstddef>

#define BB 16
#define LTEXT 128
#define LVIS 4096
#define DD 1024
#define HH 16
#define HD 64

// ---------------- scratch (device globals: the sanctioned no-alloc workaround) ----
// g_V doubles as the attention-output buffer for pass2 (V is dead after pass1).
__device__ __align__(256) float g_Q[BB * LTEXT * DD];          // 8 MB   (b*128+t, 1024)
__device__ __align__(256) float g_K[(size_t)BB * LVIS * DD];   // 268 MB (b*4096+s, 1024)
__device__ __align__(256) float g_V[(size_t)BB * LVIS * DD];   // 268 MB (later: AO)
__device__ __align__(256) float g_TGV[BB * HH * LTEXT * HD];   // 8 MB   (bh*128+t, 64)
__device__ __align__(256) float g_M[BB * HH * LTEXT];
__device__ __align__(256) float g_L[BB * HH * LTEXT];

// ---------------- packed fp32x2 helpers (sm_103a) ---------------------------------
__device__ __forceinline__ unsigned long long pack2(float v) {
    unsigned long long r;
    asm("mov.b64 %0, {%1, %1};" : "=l"(r) : "f"(v));
    return r;
}
__device__ __forceinline__ void fma2(unsigned long long& c, unsigned long long a,
                                     unsigned long long b) {
    asm("fma.rn.f32x2 %0, %1, %2, %0;" : "+l"(c) : "l"(a), "l"(b));
}
__device__ __forceinline__ void mul2(unsigned long long& c, unsigned long long a) {
    asm("mul.rn.f32x2 %0, %0, %1;" : "+l"(c) : "l"(a));
}
__device__ __forceinline__ float2 unpk2(unsigned long long v) {
    float2 f;
    asm("mov.b64 {%0, %1}, %2;" : "=f"(f.x), "=f"(f.y) : "l"(v));
    return f;
}

// ---------------- generic GEMM: C[M,1024] = alpha*(A[M,1024] @ W[1024,1024] + bias)
// 128x128 tile, BK=16, 256 threads, 8x8 per thread via f32x2.
// a_sel: 0 = A param, 1 = g_V.   c_sel: 0 = C param, 1 = g_Q, 2 = g_K, 3 = g_V.
__global__ void __launch_bounds__(256, 2)
gemm_bias(const float* __restrict__ Ax, const float* __restrict__ W,
          const float* __restrict__ bias, float* __restrict__ Cx, float alpha,
          int a_sel, int c_sel)
{
    const float* A = (a_sel == 1) ? (const float*)g_V : Ax;
    float* C = (c_sel == 1) ? g_Q : (c_sel == 2) ? g_K : (c_sel == 3) ? g_V : Cx;

    __shared__ __align__(16) float As[16][132];   // transposed A tile [k][m]
    __shared__ __align__(16) float Bs[16][128];   // [k][n]

    const int tid = threadIdx.x;
    const int ty = tid >> 4, tx = tid & 15;
    const size_t m0 = (size_t)blockIdx.y * 128;
    const int n0 = blockIdx.x * 128;

    unsigned long long acc[8][4];
#pragma unroll
    for (int i = 0; i < 8; i++)
#pragma unroll
        for (int j = 0; j < 4; j++) acc[i][j] = 0ULL;

    for (int kt = 0; kt < 64; kt++) {
        const int k0 = kt * 16;
#pragma unroll
        for (int q = tid; q < 512; q += 256) {
            int m = q >> 2, kq = (q & 3) << 2;
            float4 a = *(const float4*)&A[(m0 + m) * 1024 + k0 + kq];
            As[kq + 0][m] = a.x; As[kq + 1][m] = a.y;
            As[kq + 2][m] = a.z; As[kq + 3][m] = a.w;
        }
#pragma unroll
        for (int q = tid; q < 512; q += 256) {
            int kk = q >> 5, c = (q & 31) << 2;
            *(float4*)&Bs[kk][c] = *(const float4*)&W[(size_t)(k0 + kk) * 1024 + n0 + c];
        }
        __syncthreads();
#pragma unroll
        for (int k = 0; k < 16; k++) {
            float4 a0 = *(float4*)&As[k][ty * 8];
            float4 a1 = *(float4*)&As[k][ty * 8 + 4];
            ulonglong2 b0 = *(ulonglong2*)&Bs[k][tx * 4];
            ulonglong2 b1 = *(ulonglong2*)&Bs[k][64 + tx * 4];
            float ar[8] = {a0.x, a0.y, a0.z, a0.w, a1.x, a1.y, a1.z, a1.w};
#pragma unroll
            for (int i = 0; i < 8; i++) {
                unsigned long long ap = pack2(ar[i]);
                fma2(acc[i][0], ap, b0.x);
                fma2(acc[i][1], ap, b0.y);
                fma2(acc[i][2], ap, b1.x);
                fma2(acc[i][3], ap, b1.y);
            }
        }
        __syncthreads();
    }
#pragma unroll
    for (int i = 0; i < 8; i++) {
        size_t m = m0 + ty * 8 + i;
#pragma unroll
        for (int ch = 0; ch < 2; ch++) {
            int c = n0 + ch * 64 + tx * 4;
            float2 p0 = unpk2(acc[i][ch * 2 + 0]);
            float2 p1 = unpk2(acc[i][ch * 2 + 1]);
            float4 o;
            o.x = alpha * (p0.x + bias[c + 0]);
            o.y = alpha * (p0.y + bias[c + 1]);
            o.z = alpha * (p1.x + bias[c + 2]);
            o.w = alpha * (p1.y + bias[c + 3]);
            *(float4*)&C[m * 1024 + c] = o;
        }
    }
}

// ---------------- attention pass 1: flash over s, tgv = softmax(QK^T) @ V ---------
#define SPAD 68          // 64-wide head rows + pad
#define PPAD 132         // 128-wide P rows + pad   (R2 bug: was 65 -> smem OOB)
#define P1_SMEM ((3 * 128 * SPAD + 128 * PPAD) * 4)

__global__ void __launch_bounds__(256, 1)
attn_pass1()
{
    extern __shared__ __align__(16) float sm[];
    float* qs = sm;                    // [128][SPAD] q rows t
    float* ks = qs + 128 * SPAD;       // [128][SPAD] k rows s
    float* vs = ks + 128 * SPAD;       // [128][SPAD] v rows s
    float* ps = vs + 128 * SPAD;       // [128][PPAD] P[t][s]

    const int tid = threadIdx.x;
    const int ty = tid >> 4, tx = tid & 15;
    const int bh = blockIdx.x;
    const int b = bh >> 4, h = bh & 15;

    const float* qbase = g_Q + (size_t)b * LTEXT * DD + h * HD;
    for (int q = tid; q < 2048; q += 256) {
        int t = q >> 4, k4 = (q & 15) << 2;
        *(float4*)&qs[t * SPAD + k4] = *(const float4*)&qbase[(size_t)t * DD + k4];
    }

    float m_i[8], l_i[8];
    unsigned long long Opk[8][2];
#pragma unroll
    for (int i = 0; i < 8; i++) {
        m_i[i] = -1e30f; l_i[i] = 0.f; Opk[i][0] = 0ULL; Opk[i][1] = 0ULL;
    }

    for (int cc = 0; cc < LVIS / 128; cc++) {
        const int s0 = cc * 128;
        __syncthreads();   // previous PV (reads ks/vs/ps) must finish
        const float* kbase = g_K + (size_t)(b * LVIS + s0) * DD + h * HD;
        const float* vbase = g_V + (size_t)(b * LVIS + s0) * DD + h * HD;
        for (int q = tid; q < 2048; q += 256) {
            int s = q >> 4, k4 = (q & 15) << 2;
            *(float4*)&ks[s * SPAD + k4] = *(const float4*)&kbase[(size_t)s * DD + k4];
            *(float4*)&vs[s * SPAD + k4] = *(const float4*)&vbase[(size_t)s * DD + k4];
        }
        __syncthreads();

        float S[8][8];
#pragma unroll
        for (int i = 0; i < 8; i++)
#pragma unroll
            for (int j = 0; j < 8; j++) S[i][j] = 0.f;

#pragma unroll
        for (int k4 = 0; k4 < 16; k4++) {
            float4 a[8];
#pragma unroll
            for (int i = 0; i < 8; i++)
                a[i] = *(float4*)&qs[(ty * 8 + i) * SPAD + k4 * 4];
#pragma unroll
            for (int j = 0; j < 8; j++) {
                float4 bb = *(float4*)&ks[(tx + 16 * j) * SPAD + k4 * 4];
#pragma unroll
                for (int i = 0; i < 8; i++)
                    S[i][j] += a[i].x * bb.x + a[i].y * bb.y + a[i].z * bb.z + a[i].w * bb.w;
            }
        }

        // online softmax update (row t spread over 16 lanes; reduce via shfl)
#pragma unroll
        for (int i = 0; i < 8; i++) {
            float mx = S[i][0];
#pragma unroll
            for (int j = 1; j < 8; j++) mx = fmaxf(mx, S[i][j]);
#pragma unroll
            for (int off = 8; off; off >>= 1)
                mx = fmaxf(mx, __shfl_xor_sync(0xffffffffu, mx, off));
            float mnew = fmaxf(m_i[i], mx);
            float corr = __expf(m_i[i] - mnew);
            float rs = 0.f;
#pragma unroll
            for (int j = 0; j < 8; j++) {
                float p = __expf(S[i][j] - mnew);
                S[i][j] = p; rs += p;
            }
#pragma unroll
            for (int off = 8; off; off >>= 1)
                rs += __shfl_xor_sync(0xffffffffu, rs, off);
            l_i[i] = l_i[i] * corr + rs;
            m_i[i] = mnew;
            unsigned long long cp = pack2(corr);
            mul2(Opk[i][0], cp);
            mul2(Opk[i][1], cp);
#pragma unroll
            for (int j = 0; j < 8; j++)
                ps[(ty * 8 + i) * PPAD + tx + 16 * j] = S[i][j];
        }
        __syncthreads();

        // O[t, tx*4..+3] += P[t,s] * V[s,d]
#pragma unroll 4
        for (int s = 0; s < 128; s++) {
            ulonglong2 v4 = *(ulonglong2*)&vs[s * SPAD + tx * 4];
#pragma unroll
            for (int i = 0; i < 8; i++) {
                unsigned long long pp = pack2(ps[(ty * 8 + i) * PPAD + s]);
                fma2(Opk[i][0], pp, v4.x);
                fma2(Opk[i][1], pp, v4.y);
            }
        }
    }

#pragma unroll
    for (int i = 0; i < 8; i++) {
        int t = ty * 8 + i;
        float inv = 1.f / l_i[i];
        float2 p0 = unpk2(Opk[i][0]);
        float2 p1 = unpk2(Opk[i][1]);
        float4 o = {p0.x * inv, p0.y * inv, p1.x * inv, p1.y * inv};
        *(float4*)&g_TGV[((size_t)bh * 128 + t) * 64 + tx * 4] = o;
        if (tx == 0) {
            g_M[bh * 128 + t] = m_i[i];
            g_L[bh * 128 + t] = l_i[i];
        }
    }
}

// ---------------- attention pass 2: AO[s,:] = sum_t P[t,s] * tgv[t,:] -------------
// Writes into g_V (V is dead after pass1).
#define P2_SMEM ((3 * 128 * SPAD + 128 * PPAD + 256) * 4)

__global__ void __launch_bounds__(256, 1)
attn_pass2()
{
    extern __shared__ __align__(16) float sm2[];
    float* qs = sm2;                   // [128][SPAD] q rows t
    float* ks = qs + 128 * SPAD;       // [128][SPAD] k rows s (this chunk)
    float* ts = ks + 128 * SPAD;       // [128][SPAD] tgv rows t
    float* ps = ts + 128 * SPAD;       // [128][PPAD] P^T[s][t]
    float* msm = ps + 128 * PPAD;      // [128]
    float* lsm = msm + 128;            // [128]

    const int tid = threadIdx.x;
    const int ty = tid >> 4, tx = tid & 15;
    const int cc = blockIdx.x;         // s chunk
    const int bh = blockIdx.y;
    const int b = bh >> 4, h = bh & 15;
    const int s0 = cc * 128;

    const float* qbase = g_Q + (size_t)b * LTEXT * DD + h * HD;
    const float* kbase = g_K + (size_t)(b * LVIS + s0) * DD + h * HD;
    for (int q = tid; q < 2048; q += 256) {
        int r = q >> 4, k4 = (q & 15) << 2;
        *(float4*)&qs[r * SPAD + k4] = *(const float4*)&qbase[(size_t)r * DD + k4];
        *(float4*)&ks[r * SPAD + k4] = *(const float4*)&kbase[(size_t)r * DD + k4];
        *(float4*)&ts[r * SPAD + k4] =
            *(const float4*)&g_TGV[((size_t)bh * 128 + r) * 64 + k4];
    }
    if (tid < 128) {
        msm[tid] = g_M[bh * 128 + tid];
        lsm[tid] = g_L[bh * 128 + tid];
    }
    __syncthreads();

    // S^T[s][t] = k[s] . q[t]
    float S[8][8];
#pragma unroll
    for (int i = 0; i < 8; i++)
#pragma unroll
        for (int j = 0; j < 8; j++) S[i][j] = 0.f;

#pragma unroll
    for (int k4 = 0; k4 < 16; k4++) {
        float4 a[8];
#pragma unroll
        for (int i = 0; i < 8; i++)
            a[i] = *(float4*)&ks[(ty * 8 + i) * SPAD + k4 * 4];
#pragma unroll
        for (int j = 0; j < 8; j++) {
            float4 bb = *(float4*)&qs[(tx + 16 * j) * SPAD + k4 * 4];
#pragma unroll
            for (int i = 0; i < 8; i++)
                S[i][j] += a[i].x * bb.x + a[i].y * bb.y + a[i].z * bb.z + a[i].w * bb.w;
        }
    }

    float mm[8], rl[8];
#pragma unroll
    for (int j = 0; j < 8; j++) {
        int t = tx + 16 * j;
        mm[j] = msm[t];
        rl[j] = 1.f / lsm[t];
    }
#pragma unroll
    for (int i = 0; i < 8; i++)
#pragma unroll
        for (int j = 0; j < 8; j++)
            ps[(ty * 8 + i) * PPAD + tx + 16 * j] = __expf(S[i][j] - mm[j]) * rl[j];
    __syncthreads();

    unsigned long long Opk[8][2];
#pragma unroll
    for (int i = 0; i < 8; i++) { Opk[i][0] = 0ULL; Opk[i][1] = 0ULL; }

#pragma unroll 4
    for (int t = 0; t < 128; t++) {
        ulonglong2 v4 = *(ulonglong2*)&ts[t * SPAD + tx * 4];
#pragma unroll
        for (int i = 0; i < 8; i++) {
            unsigned long long pp = pack2(ps[(ty * 8 + i) * PPAD + t]);
            fma2(Opk[i][0], pp, v4.x);
            fma2(Opk[i][1], pp, v4.y);
        }
    }

#pragma unroll
    for (int i = 0; i < 8; i++) {
        int s = s0 + ty * 8 + i;
        float2 p0 = unpk2(Opk[i][0]);
        float2 p1 = unpk2(Opk[i][1]);
        float4 o = {p0.x, p0.y, p1.x, p1.y};
        *(float4*)&g_V[(size_t)(b * LVIS + s) * DD + h * HD + tx * 4] = o;
    }
}

// ---------------- launch ----------------------------------------------------------
extern "C" void kernel_launch(void* const* d_in, const int* in_sizes, int n_in,
                              void* d_out, int out_size)
{
    // Resolve inputs BY SIZE (element counts are role-unique):
    //   67108864 -> hidden_states, 2097152 -> text_states,
    //   1048576  -> weights (encounter order q,k,v,o), 1024 -> biases (q,k,v,o).
    const float* hidden = nullptr;
    const float* text = nullptr;
    const float* Ws[4] = {nullptr, nullptr, nullptr, nullptr};
    const float* bs[4] = {nullptr, nullptr, nullptr, nullptr};
    int nw = 0, nb = 0;
    for (int i = 0; i < n_in; i++) {
        int sz = in_sizes[i];
        const float* p = (const float*)d_in[i];
        if (sz == BB * LVIS * DD) { if (!hidden) hidden = p; }
        else if (sz == LTEXT * BB * DD) { if (!text) text = p; }
        else if (sz == DD * DD) { if (nw < 4) Ws[nw++] = p; }
        else if (sz == DD) { if (nb < 4) bs[nb++] = p; }
    }
    // Positional fallback if size matching ever fails.
    if (!hidden) hidden = (const float*)d_in[0];
    if (!text) text = (const float*)d_in[1];
    if (nw < 4) { Ws[0]=(const float*)d_in[2]; Ws[1]=(const float*)d_in[4];
                  Ws[2]=(const float*)d_in[6]; Ws[3]=(const float*)d_in[8]; }
    if (nb < 4) { bs[0]=(const float*)d_in[3]; bs[1]=(const float*)d_in[5];
                  bs[2]=(const float*)d_in[7]; bs[3]=(const float*)d_in[9]; }
    float* out = (float*)d_out;

    cudaFuncSetAttribute(attn_pass1, cudaFuncAttributeMaxDynamicSharedMemorySize, P1_SMEM);
    cudaFuncSetAttribute(attn_pass2, cudaFuncAttributeMaxDynamicSharedMemorySize, P2_SMEM);

    const float scale = 0.125f;  // HD^-0.5

    // Q proj: text_states flat rows (lt*16+b) == (b2*128+t2) rows -> identity layout.
    gemm_bias<<<dim3(8, 16), 256>>>(text, Ws[0], bs[0], nullptr, scale, 0, 1);
    gemm_bias<<<dim3(8, 512), 256>>>(hidden, Ws[1], bs[1], nullptr, 1.f, 0, 2);
    gemm_bias<<<dim3(8, 512), 256>>>(hidden, Ws[2], bs[2], nullptr, 1.f, 0, 3);

    attn_pass1<<<BB * HH, 256, P1_SMEM>>>();
    attn_pass2<<<dim3(LVIS / 128, BB * HH), 256, P2_SMEM>>>();

    // O proj reads AO from g_V.
    gemm_bias<<<dim3(8, 512), 256>>>(nullptr, Ws[3], bs[3], out, 1.f, 1, 0);
}

// round 5
// speedup vs baseline: 1.6069x; 1.6069x over previous
#include <cuda_runtime.h>
#include <cuda_bf16.h>
#include <cstdint>
#include <cstddef>

#define BB 16
#define LTEXT 128
#define LVIS 4096
#define DD 1024
#define HH 16
#define HD 64

// ---------------- scratch --------------------------------------------------------
__device__ __align__(256) float g_Q[BB * LTEXT * DD];          // 8 MB
__device__ __align__(256) float g_K[(size_t)BB * LVIS * DD];   // 268 MB
__device__ __align__(256) float g_V[(size_t)BB * LVIS * DD];   // 268 MB (later: AO)
__device__ __align__(256) float g_TGV[BB * HH * LTEXT * HD];   // 8 MB
__device__ __align__(256) float g_M[BB * HH * LTEXT];
__device__ __align__(256) float g_L[BB * HH * LTEXT];
// bf16 split buffers
__device__ __align__(256) __nv_bfloat16 g_Ah[(size_t)BB * LVIS * DD];  // 128 MB
__device__ __align__(256) __nv_bfloat16 g_Al[(size_t)BB * LVIS * DD];  // 128 MB
__device__ __align__(256) __nv_bfloat16 g_Th[BB * LTEXT * DD];         // 4 MB
__device__ __align__(256) __nv_bfloat16 g_Tl[BB * LTEXT * DD];         // 4 MB
__device__ __align__(256) __nv_bfloat16 g_Wh[4 * DD * DD];             // 8 MB (N,K major)
__device__ __align__(256) __nv_bfloat16 g_Wl[4 * DD * DD];             // 8 MB

// ---------------- helpers --------------------------------------------------------
__device__ __forceinline__ uint32_t smem_u32(const void* p) {
    uint32_t a;
    asm("{ .reg .u64 t; cvta.to.shared.u64 t, %1; cvt.u32.u64 %0, t; }" : "=r"(a) : "l"(p));
    return a;
}
__device__ __forceinline__ void ldsm4(uint32_t* r, uint32_t addr) {
    asm volatile("ldmatrix.sync.aligned.m8n8.x4.shared.b16 {%0,%1,%2,%3}, [%4];"
                 : "=r"(r[0]), "=r"(r[1]), "=r"(r[2]), "=r"(r[3]) : "r"(addr));
}
__device__ __forceinline__ void mma16816(float* d, const uint32_t* a, const uint32_t* b) {
    asm volatile("mma.sync.aligned.m16n8k16.row.col.f32.bf16.bf16.f32 "
                 "{%0,%1,%2,%3}, {%4,%5,%6,%7}, {%8,%9}, {%0,%1,%2,%3};"
                 : "+f"(d[0]), "+f"(d[1]), "+f"(d[2]), "+f"(d[3])
                 : "r"(a[0]), "r"(a[1]), "r"(a[2]), "r"(a[3]), "r"(b[0]), "r"(b[1]));
}
__device__ __forceinline__ void cp_async16(uint32_t dst, const void* src) {
    asm volatile("cp.async.cg.shared.global [%0], [%1], 16;" :: "r"(dst), "l"(src));
}

// ---------------- conversion kernels ---------------------------------------------
__global__ void convert_split(const float* __restrict__ srcp, int src_sel, int dst_sel,
                              size_t n4)
{
    const float* src = (src_sel == 1) ? (const float*)g_V : srcp;
    __nv_bfloat16* dh = dst_sel ? g_Ah : g_Th;
    __nv_bfloat16* dl = dst_sel ? g_Al : g_Tl;
    size_t stride = (size_t)gridDim.x * blockDim.x;
    for (size_t i = (size_t)blockIdx.x * blockDim.x + threadIdx.x; i < n4; i += stride) {
        float4 v = ((const float4*)src)[i];
        __nv_bfloat16 h0 = __float2bfloat16(v.x), h1 = __float2bfloat16(v.y);
        __nv_bfloat16 h2 = __float2bfloat16(v.z), h3 = __float2bfloat16(v.w);
        __nv_bfloat16 l0 = __float2bfloat16(v.x - __bfloat162float(h0));
        __nv_bfloat16 l1 = __float2bfloat16(v.y - __bfloat162float(h1));
        __nv_bfloat16 l2 = __float2bfloat16(v.z - __bfloat162float(h2));
        __nv_bfloat16 l3 = __float2bfloat16(v.w - __bfloat162float(h3));
        __nv_bfloat162 hh[2] = {{h0, h1}, {h2, h3}};
        __nv_bfloat162 ll[2] = {{l0, l1}, {l2, l3}};
        ((uint2*)dh)[i] = *(uint2*)hh;
        ((uint2*)dl)[i] = *(uint2*)ll;
    }
}

// W[K,N] fp32 -> Wt_hi/lo[N,K] bf16 (tiled transpose)
__global__ void convert_wt(const float* __restrict__ W, int widx)
{
    __shared__ float t[32][33];
    int tx = threadIdx.x, ty = threadIdx.y;   // (32,8)
    int n = blockIdx.x * 32 + tx;
    int k0 = blockIdx.y * 32;
#pragma unroll
    for (int j = 0; j < 32; j += 8)
        t[ty + j][tx] = W[(size_t)(k0 + ty + j) * DD + n];
    __syncthreads();
    __nv_bfloat16* wh = g_Wh + (size_t)widx * DD * DD;
    __nv_bfloat16* wl = g_Wl + (size_t)widx * DD * DD;
    int k = k0 + tx;
    int nn0 = blockIdx.x * 32;
#pragma unroll
    for (int j = 0; j < 32; j += 8) {
        float v = t[tx][ty + j];
        __nv_bfloat16 h = __float2bfloat16(v);
        __nv_bfloat16 l = __float2bfloat16(v - __bfloat162float(h));
        wh[(size_t)(nn0 + ty + j) * DD + k] = h;
        wl[(size_t)(nn0 + ty + j) * DD + k] = l;
    }
}

// ---------------- split-bf16 GEMM on mma.sync (HMMA) ------------------------------
// C[M,1024] = alpha*(A@W + bias). A hi/lo K-major [M,K]; W hi/lo (N,K)-major.
// 128x128 tile, BK=32, 8 warps (2 M x 4 N), warp tile 64x32, m16n8k16.
#define APAD 40                      // bf16 row stride (conflict-free ldmatrix)
#define TILE_B (128 * APAD * 2)      // 10240 B per tile
#define STAGE_B (4 * TILE_B)         // Ah,Al,Bh,Bl
#define G_SMEM (2 * STAGE_B)         // 81920 B, double buffered

__global__ void __launch_bounds__(256)
gemm_mma(int a_sel, int w_idx, const float* __restrict__ bias, float* __restrict__ Cx,
         int c_sel, float alpha)
{
    extern __shared__ __align__(256) char smem[];
    const uint32_t sb = smem_u32(smem);
    const int tid = threadIdx.x;
    const int wid = tid >> 5, lane = tid & 31;
    const int warp_m = wid & 1, warp_n = wid >> 1;

    const __nv_bfloat16* Ah = a_sel ? g_Ah : g_Th;
    const __nv_bfloat16* Al = a_sel ? g_Al : g_Tl;
    const __nv_bfloat16* Bh = g_Wh + (size_t)w_idx * DD * DD;
    const __nv_bfloat16* Bl = g_Wl + (size_t)w_idx * DD * DD;
    float* C = (c_sel == 1) ? g_Q : (c_sel == 2) ? g_K : (c_sel == 3) ? g_V : Cx;

    const int n0 = blockIdx.x * 128;
    const size_t m0 = (size_t)blockIdx.y * 128;

    float acc[4][4][4] = {};

    auto issue = [&](int kt, int stage) {
        const int k0 = kt * 32;
        const uint32_t sdst = sb + stage * STAGE_B;
#pragma unroll
        for (int i = 0; i < 8; i++) {
            int q = tid + i * 256;
            int tile = q >> 9, rem = q & 511, r = rem >> 2, seg = rem & 3;
            const __nv_bfloat16* src;
            if (tile == 0)      src = Ah + (m0 + r) * DD + k0 + seg * 8;
            else if (tile == 1) src = Al + (m0 + r) * DD + k0 + seg * 8;
            else if (tile == 2) src = Bh + (size_t)(n0 + r) * DD + k0 + seg * 8;
            else                src = Bl + (size_t)(n0 + r) * DD + k0 + seg * 8;
            cp_async16(sdst + tile * TILE_B + (r * APAD + seg * 8) * 2, src);
        }
        asm volatile("cp.async.commit_group;" ::: "memory");
    };

    issue(0, 0);
    for (int kt = 0; kt < 32; kt++) {
        if (kt + 1 < 32) {
            issue(kt + 1, (kt + 1) & 1);
            asm volatile("cp.async.wait_group 1;" ::: "memory");
        } else {
            asm volatile("cp.async.wait_group 0;" ::: "memory");
        }
        __syncthreads();

        const uint32_t so = sb + (kt & 1) * STAGE_B;
#pragma unroll
        for (int ks = 0; ks < 2; ks++) {
            uint32_t ah[4][4], alr[4][4], bh[2][4], blr[2][4];
            const int arow = warp_m * 64 + (lane & 15);
            const int acol = ks * 16 + (lane >> 4) * 8;
#pragma unroll
            for (int mi = 0; mi < 4; mi++) {
                uint32_t off = ((arow + mi * 16) * APAD + acol) * 2;
                ldsm4(ah[mi], so + off);
                ldsm4(alr[mi], so + TILE_B + off);
            }
            const int lm = lane & 7, quad = lane >> 3;
            const int brow = warp_n * 32 + ((quad & 2) ? 8 : 0) + lm;
            const int bcol = ks * 16 + (quad & 1) * 8;
#pragma unroll
            for (int np = 0; np < 2; np++) {
                uint32_t off = ((brow + np * 16) * APAD + bcol) * 2;
                ldsm4(bh[np], so + 2 * TILE_B + off);
                ldsm4(blr[np], so + 3 * TILE_B + off);
            }
#pragma unroll
            for (int mi = 0; mi < 4; mi++)
#pragma unroll
                for (int ni = 0; ni < 4; ni++) {
                    const uint32_t* bhp = &bh[ni >> 1][(ni & 1) * 2];
                    const uint32_t* blp = &blr[ni >> 1][(ni & 1) * 2];
                    mma16816(acc[mi][ni], ah[mi], bhp);
                    mma16816(acc[mi][ni], alr[mi], bhp);
                    mma16816(acc[mi][ni], ah[mi], blp);
                }
        }
        __syncthreads();
    }

    // epilogue
#pragma unroll
    for (int ni = 0; ni < 4; ni++) {
        const int col = n0 + warp_n * 32 + ni * 8 + (lane & 3) * 2;
        const float b0 = bias[col], b1 = bias[col + 1];
#pragma unroll
        for (int mi = 0; mi < 4; mi++) {
            const size_t r0 = m0 + warp_m * 64 + mi * 16 + (lane >> 2);
            float2 o0 = {alpha * (acc[mi][ni][0] + b0), alpha * (acc[mi][ni][1] + b1)};
            float2 o1 = {alpha * (acc[mi][ni][2] + b0), alpha * (acc[mi][ni][3] + b1)};
            *(float2*)&C[r0 * DD + col] = o0;
            *(float2*)&C[(r0 + 8) * DD + col] = o1;
        }
    }
}

// ---------------- attention (fp32, unchanged from R3 pass) ------------------------
__device__ __forceinline__ unsigned long long pack2(float v) {
    unsigned long long r;
    asm("mov.b64 %0, {%1, %1};" : "=l"(r) : "f"(v));
    return r;
}
__device__ __forceinline__ void fma2(unsigned long long& c, unsigned long long a,
                                     unsigned long long b) {
    asm("fma.rn.f32x2 %0, %1, %2, %0;" : "+l"(c) : "l"(a), "l"(b));
}
__device__ __forceinline__ void mul2(unsigned long long& c, unsigned long long a) {
    asm("mul.rn.f32x2 %0, %0, %1;" : "+l"(c) : "l"(a));
}
__device__ __forceinline__ float2 unpk2(unsigned long long v) {
    float2 f;
    asm("mov.b64 {%0, %1}, %2;" : "=f"(f.x), "=f"(f.y) : "l"(v));
    return f;
}

#define SPAD 68
#define PPAD 132
#define P1_SMEM ((3 * 128 * SPAD + 128 * PPAD) * 4)

__global__ void __launch_bounds__(256, 1)
attn_pass1()
{
    extern __shared__ __align__(16) float sm[];
    float* qs = sm;
    float* ks = qs + 128 * SPAD;
    float* vs = ks + 128 * SPAD;
    float* ps = vs + 128 * SPAD;

    const int tid = threadIdx.x;
    const int ty = tid >> 4, tx = tid & 15;
    const int bh = blockIdx.x;
    const int b = bh >> 4, h = bh & 15;

    const float* qbase = g_Q + (size_t)b * LTEXT * DD + h * HD;
    for (int q = tid; q < 2048; q += 256) {
        int t = q >> 4, k4 = (q & 15) << 2;
        *(float4*)&qs[t * SPAD + k4] = *(const float4*)&qbase[(size_t)t * DD + k4];
    }

    float m_i[8], l_i[8];
    unsigned long long Opk[8][2];
#pragma unroll
    for (int i = 0; i < 8; i++) {
        m_i[i] = -1e30f; l_i[i] = 0.f; Opk[i][0] = 0ULL; Opk[i][1] = 0ULL;
    }

    for (int cc = 0; cc < LVIS / 128; cc++) {
        const int s0 = cc * 128;
        __syncthreads();
        const float* kbase = g_K + (size_t)(b * LVIS + s0) * DD + h * HD;
        const float* vbase = g_V + (size_t)(b * LVIS + s0) * DD + h * HD;
        for (int q = tid; q < 2048; q += 256) {
            int s = q >> 4, k4 = (q & 15) << 2;
            *(float4*)&ks[s * SPAD + k4] = *(const float4*)&kbase[(size_t)s * DD + k4];
            *(float4*)&vs[s * SPAD + k4] = *(const float4*)&vbase[(size_t)s * DD + k4];
        }
        __syncthreads();

        float S[8][8];
#pragma unroll
        for (int i = 0; i < 8; i++)
#pragma unroll
            for (int j = 0; j < 8; j++) S[i][j] = 0.f;

#pragma unroll
        for (int k4 = 0; k4 < 16; k4++) {
            float4 a[8];
#pragma unroll
            for (int i = 0; i < 8; i++)
                a[i] = *(float4*)&qs[(ty * 8 + i) * SPAD + k4 * 4];
#pragma unroll
            for (int j = 0; j < 8; j++) {
                float4 bb = *(float4*)&ks[(tx + 16 * j) * SPAD + k4 * 4];
#pragma unroll
                for (int i = 0; i < 8; i++)
                    S[i][j] += a[i].x * bb.x + a[i].y * bb.y + a[i].z * bb.z + a[i].w * bb.w;
            }
        }

#pragma unroll
        for (int i = 0; i < 8; i++) {
            float mx = S[i][0];
#pragma unroll
            for (int j = 1; j < 8; j++) mx = fmaxf(mx, S[i][j]);
#pragma unroll
            for (int off = 8; off; off >>= 1)
                mx = fmaxf(mx, __shfl_xor_sync(0xffffffffu, mx, off));
            float mnew = fmaxf(m_i[i], mx);
            float corr = __expf(m_i[i] - mnew);
            float rs = 0.f;
#pragma unroll
            for (int j = 0; j < 8; j++) {
                float p = __expf(S[i][j] - mnew);
                S[i][j] = p; rs += p;
            }
#pragma unroll
            for (int off = 8; off; off >>= 1)
                rs += __shfl_xor_sync(0xffffffffu, rs, off);
            l_i[i] = l_i[i] * corr + rs;
            m_i[i] = mnew;
            unsigned long long cp = pack2(corr);
            mul2(Opk[i][0], cp);
            mul2(Opk[i][1], cp);
#pragma unroll
            for (int j = 0; j < 8; j++)
                ps[(ty * 8 + i) * PPAD + tx + 16 * j] = S[i][j];
        }
        __syncthreads();

#pragma unroll 4
        for (int s = 0; s < 128; s++) {
            ulonglong2 v4 = *(ulonglong2*)&vs[s * SPAD + tx * 4];
#pragma unroll
            for (int i = 0; i < 8; i++) {
                unsigned long long pp = pack2(ps[(ty * 8 + i) * PPAD + s]);
                fma2(Opk[i][0], pp, v4.x);
                fma2(Opk[i][1], pp, v4.y);
            }
        }
    }

#pragma unroll
    for (int i = 0; i < 8; i++) {
        int t = ty * 8 + i;
        float inv = 1.f / l_i[i];
        float2 p0 = unpk2(Opk[i][0]);
        float2 p1 = unpk2(Opk[i][1]);
        float4 o = {p0.x * inv, p0.y * inv, p1.x * inv, p1.y * inv};
        *(float4*)&g_TGV[((size_t)bh * 128 + t) * 64 + tx * 4] = o;
        if (tx == 0) {
            g_M[bh * 128 + t] = m_i[i];
            g_L[bh * 128 + t] = l_i[i];
        }
    }
}

#define P2_SMEM ((3 * 128 * SPAD + 128 * PPAD + 256) * 4)

__global__ void __launch_bounds__(256, 1)
attn_pass2()
{
    extern __shared__ __align__(16) float sm2[];
    float* qs = sm2;
    float* ks = qs + 128 * SPAD;
    float* ts = ks + 128 * SPAD;
    float* ps = ts + 128 * SPAD;
    float* msm = ps + 128 * PPAD;
    float* lsm = msm + 128;

    const int tid = threadIdx.x;
    const int ty = tid >> 4, tx = tid & 15;
    const int cc = blockIdx.x;
    const int bh = blockIdx.y;
    const int b = bh >> 4, h = bh & 15;
    const int s0 = cc * 128;

    const float* qbase = g_Q + (size_t)b * LTEXT * DD + h * HD;
    const float* kbase = g_K + (size_t)(b * LVIS + s0) * DD + h * HD;
    for (int q = tid; q < 2048; q += 256) {
        int r = q >> 4, k4 = (q & 15) << 2;
        *(float4*)&qs[r * SPAD + k4] = *(const float4*)&qbase[(size_t)r * DD + k4];
        *(float4*)&ks[r * SPAD + k4] = *(const float4*)&kbase[(size_t)r * DD + k4];
        *(float4*)&ts[r * SPAD + k4] =
            *(const float4*)&g_TGV[((size_t)bh * 128 + r) * 64 + k4];
    }
    if (tid < 128) {
        msm[tid] = g_M[bh * 128 + tid];
        lsm[tid] = g_L[bh * 128 + tid];
    }
    __syncthreads();

    float S[8][8];
#pragma unroll
    for (int i = 0; i < 8; i++)
#pragma unroll
        for (int j = 0; j < 8; j++) S[i][j] = 0.f;

#pragma unroll
    for (int k4 = 0; k4 < 16; k4++) {
        float4 a[8];
#pragma unroll
        for (int i = 0; i < 8; i++)
            a[i] = *(float4*)&ks[(ty * 8 + i) * SPAD + k4 * 4];
#pragma unroll
        for (int j = 0; j < 8; j++) {
            float4 bb = *(float4*)&qs[(tx + 16 * j) * SPAD + k4 * 4];
#pragma unroll
            for (int i = 0; i < 8; i++)
                S[i][j] += a[i].x * bb.x + a[i].y * bb.y + a[i].z * bb.z + a[i].w * bb.w;
        }
    }

    float mm[8], rl[8];
#pragma unroll
    for (int j = 0; j < 8; j++) {
        int t = tx + 16 * j;
        mm[j] = msm[t];
        rl[j] = 1.f / lsm[t];
    }
#pragma unroll
    for (int i = 0; i < 8; i++)
#pragma unroll
        for (int j = 0; j < 8; j++)
            ps[(ty * 8 + i) * PPAD + tx + 16 * j] = __expf(S[i][j] - mm[j]) * rl[j];
    __syncthreads();

    unsigned long long Opk[8][2];
#pragma unroll
    for (int i = 0; i < 8; i++) { Opk[i][0] = 0ULL; Opk[i][1] = 0ULL; }

#pragma unroll 4
    for (int t = 0; t < 128; t++) {
        ulonglong2 v4 = *(ulonglong2*)&ts[t * SPAD + tx * 4];
#pragma unroll
        for (int i = 0; i < 8; i++) {
            unsigned long long pp = pack2(ps[(ty * 8 + i) * PPAD + t]);
            fma2(Opk[i][0], pp, v4.x);
            fma2(Opk[i][1], pp, v4.y);
        }
    }

#pragma unroll
    for (int i = 0; i < 8; i++) {
        int s = s0 + ty * 8 + i;
        float2 p0 = unpk2(Opk[i][0]);
        float2 p1 = unpk2(Opk[i][1]);
        float4 o = {p0.x, p0.y, p1.x, p1.y};
        *(float4*)&g_V[(size_t)(b * LVIS + s) * DD + h * HD + tx * 4] = o;
    }
}

// ---------------- launch ----------------------------------------------------------
extern "C" void kernel_launch(void* const* d_in, const int* in_sizes, int n_in,
                              void* d_out, int out_size)
{
    const float* hidden = nullptr;
    const float* text = nullptr;
    const float* Ws[4] = {nullptr, nullptr, nullptr, nullptr};
    const float* bs[4] = {nullptr, nullptr, nullptr, nullptr};
    int nw = 0, nb = 0;
    for (int i = 0; i < n_in; i++) {
        int sz = in_sizes[i];
        const float* p = (const float*)d_in[i];
        if (sz == BB * LVIS * DD) { if (!hidden) hidden = p; }
        else if (sz == LTEXT * BB * DD) { if (!text) text = p; }
        else if (sz == DD * DD) { if (nw < 4) Ws[nw++] = p; }
        else if (sz == DD) { if (nb < 4) bs[nb++] = p; }
    }
    if (!hidden) hidden = (const float*)d_in[0];
    if (!text) text = (const float*)d_in[1];
    if (nw < 4) { Ws[0]=(const float*)d_in[2]; Ws[1]=(const float*)d_in[4];
                  Ws[2]=(const float*)d_in[6]; Ws[3]=(const float*)d_in[8]; }
    if (nb < 4) { bs[0]=(const float*)d_in[3]; bs[1]=(const float*)d_in[5];
                  bs[2]=(const float*)d_in[7]; bs[3]=(const float*)d_in[9]; }
    float* out = (float*)d_out;

    cudaFuncSetAttribute(gemm_mma, cudaFuncAttributeMaxDynamicSharedMemorySize, G_SMEM);
    cudaFuncSetAttribute(attn_pass1, cudaFuncAttributeMaxDynamicSharedMemorySize, P1_SMEM);
    cudaFuncSetAttribute(attn_pass2, cudaFuncAttributeMaxDynamicSharedMemorySize, P2_SMEM);

    // weight transpose+split
    for (int w = 0; w < 4; w++)
        convert_wt<<<dim3(32, 32), dim3(32, 8)>>>(Ws[w], w);
    // activation splits
    convert_split<<<2048, 256>>>(text, 0, 0, (size_t)LTEXT * BB * DD / 4);
    convert_split<<<8192, 256>>>(hidden, 0, 1, (size_t)BB * LVIS * DD / 4);

    // projections on tensor cores (mma.sync)
    gemm_mma<<<dim3(8, 16), 256, G_SMEM>>>(0, 0, bs[0], nullptr, 1, 0.125f);   // Q
    gemm_mma<<<dim3(8, 512), 256, G_SMEM>>>(1, 1, bs[1], nullptr, 2, 1.f);     // K
    gemm_mma<<<dim3(8, 512), 256, G_SMEM>>>(1, 2, bs[2], nullptr, 3, 1.f);     // V

    attn_pass1<<<BB * HH, 256, P1_SMEM>>>();
    attn_pass2<<<dim3(LVIS / 128, BB * HH), 256, P2_SMEM>>>();

    // O projection: AO lives in g_V
    convert_split<<<8192, 256>>>(nullptr, 1, 1, (size_t)BB * LVIS * DD / 4);
    gemm_mma<<<dim3(8, 512), 256, G_SMEM>>>(1, 3, bs[3], out, 0, 1.f);         // O
}

// round 7
// speedup vs baseline: 2.1320x; 1.3268x over previous
#include <cuda_runtime.h>
#include <cuda_bf16.h>
#include <cstdint>
#include <cstddef>

#define BB 16
#define LTEXT 128
#define LVIS 4096
#define DD 1024
#define HH 16
#define HD 64

// ---------------- scratch (bf16 hi/lo is the native interchange format) -----------
__device__ __align__(256) __nv_bfloat16 g_Ah[(size_t)BB * LVIS * DD];  // hidden hi
__device__ __align__(256) __nv_bfloat16 g_Al[(size_t)BB * LVIS * DD];  // hidden lo
__device__ __align__(256) __nv_bfloat16 g_Th[BB * LTEXT * DD];         // text hi
__device__ __align__(256) __nv_bfloat16 g_Tl[BB * LTEXT * DD];         // text lo
__device__ __align__(256) __nv_bfloat16 g_Wh[4 * DD * DD];             // W (N,K) hi
__device__ __align__(256) __nv_bfloat16 g_Wl[4 * DD * DD];             // W (N,K) lo
__device__ __align__(256) __nv_bfloat16 g_Qh[BB * LTEXT * DD];
__device__ __align__(256) __nv_bfloat16 g_Ql[BB * LTEXT * DD];
__device__ __align__(256) __nv_bfloat16 g_Kh[(size_t)BB * LVIS * DD];  // K, later AO hi
__device__ __align__(256) __nv_bfloat16 g_Kl[(size_t)BB * LVIS * DD];  // K, later AO lo
__device__ __align__(256) __nv_bfloat16 g_Vh[(size_t)BB * LVIS * DD];
__device__ __align__(256) __nv_bfloat16 g_Vl[(size_t)BB * LVIS * DD];
__device__ __align__(256) __nv_bfloat16 g_TGVh[BB * HH * LTEXT * HD];
__device__ __align__(256) __nv_bfloat16 g_TGVl[BB * HH * LTEXT * HD];
__device__ __align__(256) float g_M[BB * HH * LTEXT];
__device__ __align__(256) float g_L[BB * HH * LTEXT];

// ---------------- helpers --------------------------------------------------------
__device__ __forceinline__ uint32_t smem_u32(const void* p) {
    uint32_t a;
    asm("{ .reg .u64 t; cvta.to.shared.u64 t, %1; cvt.u32.u64 %0, t; }" : "=r"(a) : "l"(p));
    return a;
}
__device__ __forceinline__ void ldsm4(uint32_t* r, uint32_t addr) {
    asm volatile("ldmatrix.sync.aligned.m8n8.x4.shared.b16 {%0,%1,%2,%3}, [%4];"
                 : "=r"(r[0]), "=r"(r[1]), "=r"(r[2]), "=r"(r[3]) : "r"(addr));
}
__device__ __forceinline__ void ldsm4t(uint32_t* r, uint32_t addr) {
    asm volatile("ldmatrix.sync.aligned.m8n8.x4.trans.shared.b16 {%0,%1,%2,%3}, [%4];"
                 : "=r"(r[0]), "=r"(r[1]), "=r"(r[2]), "=r"(r[3]) : "r"(addr));
}
__device__ __forceinline__ void mma16816(float* d, const uint32_t* a, const uint32_t* b) {
    asm volatile("mma.sync.aligned.m16n8k16.row.col.f32.bf16.bf16.f32 "
                 "{%0,%1,%2,%3}, {%4,%5,%6,%7}, {%8,%9}, {%0,%1,%2,%3};"
                 : "+f"(d[0]), "+f"(d[1]), "+f"(d[2]), "+f"(d[3])
                 : "r"(a[0]), "r"(a[1]), "r"(a[2]), "r"(a[3]), "r"(b[0]), "r"(b[1]));
}
__device__ __forceinline__ void cp_async16(uint32_t dst, const void* src) {
    asm volatile("cp.async.cg.shared.global [%0], [%1], 16;" :: "r"(dst), "l"(src));
}
#define CP_COMMIT() asm volatile("cp.async.commit_group;" ::: "memory")
#define CP_WAIT0() asm volatile("cp.async.wait_group 0;" ::: "memory")

__device__ __forceinline__ uint32_t packbf(float lo, float hi) {
    __nv_bfloat16 l = __float2bfloat16(lo), h = __float2bfloat16(hi);
    uint16_t lu = *(uint16_t*)&l, hu = *(uint16_t*)&h;
    return (uint32_t)lu | ((uint32_t)hu << 16);
}
__device__ __forceinline__ float bfres(float v, float* hi) {
    __nv_bfloat16 h = __float2bfloat16(v);
    *hi = __bfloat162float(h);
    return v - *hi;
}

// ---------------- conversion kernels ---------------------------------------------
__global__ void convert_split(const float* __restrict__ src, int dst_sel, size_t n4)
{
    __nv_bfloat16* dh = dst_sel ? g_Ah : g_Th;
    __nv_bfloat16* dl = dst_sel ? g_Al : g_Tl;
    size_t stride = (size_t)gridDim.x * blockDim.x;
    for (size_t i = (size_t)blockIdx.x * blockDim.x + threadIdx.x; i < n4; i += stride) {
        float4 v = ((const float4*)src)[i];
        float h0, h1, h2, h3;
        float l0 = bfres(v.x, &h0), l1 = bfres(v.y, &h1);
        float l2 = bfres(v.z, &h2), l3 = bfres(v.w, &h3);
        uint2 ph = {packbf(h0, h1), packbf(h2, h3)};
        uint2 pl = {packbf(l0, l1), packbf(l2, l3)};
        ((uint2*)dh)[i] = ph;
        ((uint2*)dl)[i] = pl;
    }
}

__global__ void convert_wt(const float* __restrict__ W, int widx)
{
    __shared__ float t[32][33];
    int tx = threadIdx.x, ty = threadIdx.y;   // (32,8)
    int n = blockIdx.x * 32 + tx;
    int k0 = blockIdx.y * 32;
#pragma unroll
    for (int j = 0; j < 32; j += 8)
        t[ty + j][tx] = W[(size_t)(k0 + ty + j) * DD + n];
    __syncthreads();
    __nv_bfloat16* wh = g_Wh + (size_t)widx * DD * DD;
    __nv_bfloat16* wl = g_Wl + (size_t)widx * DD * DD;
    int k = k0 + tx;
    int nn0 = blockIdx.x * 32;
#pragma unroll
    for (int j = 0; j < 32; j += 8) {
        float v = t[tx][ty + j];
        float h;
        float l = bfres(v, &h);
        wh[(size_t)(nn0 + ty + j) * DD + k] = __float2bfloat16(h);
        wl[(size_t)(nn0 + ty + j) * DD + k] = __float2bfloat16(l);
    }
}

// ---------------- split-bf16 GEMM on mma.sync -------------------------------------
// a_sel: 0 = text (Th/Tl), 1 = hidden (Ah/Al), 2 = AO (Kh/Kl)
// c_mode: 0 = fp32 Cx, 1 = Qh/Ql, 2 = Kh/Kl, 3 = Vh/Vl
#define APAD 40
#define TILE_B (128 * APAD * 2)
#define STAGE_B (4 * TILE_B)
#define G_SMEM (2 * STAGE_B)

__global__ void __launch_bounds__(256)
gemm_mma(int a_sel, int w_idx, const float* __restrict__ bias, float* __restrict__ Cx,
         int c_mode, float alpha)
{
    extern __shared__ __align__(256) char smem[];
    const uint32_t sb = smem_u32(smem);
    const int tid = threadIdx.x;
    const int wid = tid >> 5, lane = tid & 31;
    const int warp_m = wid & 1, warp_n = wid >> 1;

    const __nv_bfloat16* Ah = (a_sel == 0) ? g_Th : (a_sel == 1) ? g_Ah : g_Kh;
    const __nv_bfloat16* Al = (a_sel == 0) ? g_Tl : (a_sel == 1) ? g_Al : g_Kl;
    const __nv_bfloat16* Bh = g_Wh + (size_t)w_idx * DD * DD;
    const __nv_bfloat16* Bl = g_Wl + (size_t)w_idx * DD * DD;

    const int n0 = blockIdx.x * 128;
    const size_t m0 = (size_t)blockIdx.y * 128;

    float acc[4][4][4] = {};

    auto issue = [&](int kt, int stage) {
        const int k0 = kt * 32;
        const uint32_t sdst = sb + stage * STAGE_B;
#pragma unroll
        for (int i = 0; i < 8; i++) {
            int q = tid + i * 256;
            int tile = q >> 9, rem = q & 511, r = rem >> 2, seg = rem & 3;
            const __nv_bfloat16* src;
            if (tile == 0)      src = Ah + (m0 + r) * DD + k0 + seg * 8;
            else if (tile == 1) src = Al + (m0 + r) * DD + k0 + seg * 8;
            else if (tile == 2) src = Bh + (size_t)(n0 + r) * DD + k0 + seg * 8;
            else                src = Bl + (size_t)(n0 + r) * DD + k0 + seg * 8;
            cp_async16(sdst + tile * TILE_B + (r * APAD + seg * 8) * 2, src);
        }
        CP_COMMIT();
    };

    issue(0, 0);
    for (int kt = 0; kt < 32; kt++) {
        if (kt + 1 < 32) {
            issue(kt + 1, (kt + 1) & 1);
            asm volatile("cp.async.wait_group 1;" ::: "memory");
        } else {
            CP_WAIT0();
        }
        __syncthreads();

        const uint32_t so = sb + (kt & 1) * STAGE_B;
#pragma unroll
        for (int ks = 0; ks < 2; ks++) {
            uint32_t ah[4][4], alr[4][4], bh[2][4], blr[2][4];
            const int arow = warp_m * 64 + (lane & 15);
            const int acol = ks * 16 + (lane >> 4) * 8;
#pragma unroll
            for (int mi = 0; mi < 4; mi++) {
                uint32_t off = ((arow + mi * 16) * APAD + acol) * 2;
                ldsm4(ah[mi], so + off);
                ldsm4(alr[mi], so + TILE_B + off);
            }
            const int lm = lane & 7, quad = lane >> 3;
            const int brow = warp_n * 32 + ((quad & 2) ? 8 : 0) + lm;
            const int bcol = ks * 16 + (quad & 1) * 8;
#pragma unroll
            for (int np = 0; np < 2; np++) {
                uint32_t off = ((brow + np * 16) * APAD + bcol) * 2;
                ldsm4(bh[np], so + 2 * TILE_B + off);
                ldsm4(blr[np], so + 3 * TILE_B + off);
            }
#pragma unroll
            for (int mi = 0; mi < 4; mi++)
#pragma unroll
                for (int ni = 0; ni < 4; ni++) {
                    const uint32_t* bhp = &bh[ni >> 1][(ni & 1) * 2];
                    const uint32_t* blp = &blr[ni >> 1][(ni & 1) * 2];
                    mma16816(acc[mi][ni], ah[mi], bhp);
                    mma16816(acc[mi][ni], alr[mi], bhp);
                    mma16816(acc[mi][ni], ah[mi], blp);
                }
        }
        __syncthreads();
    }

    // epilogue
    __nv_bfloat16* Ch = (c_mode == 1) ? g_Qh : (c_mode == 2) ? g_Kh : g_Vh;
    __nv_bfloat16* Cl = (c_mode == 1) ? g_Ql : (c_mode == 2) ? g_Kl : g_Vl;
#pragma unroll
    for (int ni = 0; ni < 4; ni++) {
        const int col = n0 + warp_n * 32 + ni * 8 + (lane & 3) * 2;
        const float b0 = bias[col], b1 = bias[col + 1];
#pragma unroll
        for (int mi = 0; mi < 4; mi++) {
            const size_t r0 = m0 + warp_m * 64 + mi * 16 + (lane >> 2);
            float v00 = alpha * (acc[mi][ni][0] + b0);
            float v01 = alpha * (acc[mi][ni][1] + b1);
            float v10 = alpha * (acc[mi][ni][2] + b0);
            float v11 = alpha * (acc[mi][ni][3] + b1);
            if (c_mode == 0) {
                *(float2*)&Cx[r0 * DD + col] = {v00, v01};
                *(float2*)&Cx[(r0 + 8) * DD + col] = {v10, v11};
            } else {
                float h00, h01, h10, h11;
                float l00 = bfres(v00, &h00), l01 = bfres(v01, &h01);
                float l10 = bfres(v10, &h10), l11 = bfres(v11, &h11);
                *(uint32_t*)&Ch[r0 * DD + col] = packbf(h00, h01);
                *(uint32_t*)&Ch[(r0 + 8) * DD + col] = packbf(h10, h11);
                *(uint32_t*)&Cl[r0 * DD + col] = packbf(l00, l01);
                *(uint32_t*)&Cl[(r0 + 8) * DD + col] = packbf(l10, l11);
            }
        }
    }
}

// ---------------- attention pass 1 on mma.sync ------------------------------------
// block = 256 threads (8 warps), one (b,h). warp w owns t-rows w*16..+15.
#define AT_STRIDE 72
#define AT_TILE (128 * AT_STRIDE * 2)   // 18432 B
#define P1_SMEM (6 * AT_TILE)           // Qh,Ql,Kh,Kl,Vh,Vl = 110592 B

__global__ void __launch_bounds__(256, 2)
attn1_mma()
{
    extern __shared__ __align__(256) char smem[];
    const uint32_t sb = smem_u32(smem);
    const int tid = threadIdx.x;
    const int wid = tid >> 5, lane = tid & 31;
    const int bh = blockIdx.x, b = bh >> 4, h = bh & 15;

    const __nv_bfloat16* Qhg = g_Qh + (size_t)(b * LTEXT) * DD + h * HD;
    const __nv_bfloat16* Qlg = g_Ql + (size_t)(b * LTEXT) * DD + h * HD;

    // Q load (2 tiles x 128 rows x 8 segs = 2048 segs)
#pragma unroll
    for (int i = 0; i < 8; i++) {
        int q = tid + i * 256;
        int tile = q >> 10, rem = q & 1023, r = rem >> 3, s = rem & 7;
        const __nv_bfloat16* src = (tile ? Qlg : Qhg) + (size_t)r * DD + s * 8;
        cp_async16(sb + tile * AT_TILE + r * (AT_STRIDE * 2) + s * 16, src);
    }

    auto issue_kv = [&](int cc) {
        const size_t row0 = (size_t)b * LVIS + cc * 128;
#pragma unroll
        for (int i = 0; i < 16; i++) {
            int q = tid + i * 256;
            int tile = q >> 10, rem = q & 1023, r = rem >> 3, s = rem & 7;
            const __nv_bfloat16* src;
            if (tile == 0)      src = g_Kh + (row0 + r) * DD + h * HD + s * 8;
            else if (tile == 1) src = g_Kl + (row0 + r) * DD + h * HD + s * 8;
            else if (tile == 2) src = g_Vh + (row0 + r) * DD + h * HD + s * 8;
            else                src = g_Vl + (row0 + r) * DD + h * HD + s * 8;
            cp_async16(sb + (2 + tile) * AT_TILE + r * (AT_STRIDE * 2) + s * 16, src);
        }
    };

    issue_kv(0);
    CP_COMMIT();
    CP_WAIT0();
    __syncthreads();

    // preload Q fragments (A operand, 4 k-steps, hi & lo)
    uint32_t qh[4][4], ql[4][4];
#pragma unroll
    for (int ks = 0; ks < 4; ks++) {
        uint32_t off = ((wid * 16 + (lane & 15)) * AT_STRIDE + ks * 16 + (lane >> 4) * 8) * 2;
        ldsm4(qh[ks], sb + off);
        ldsm4(ql[ks], sb + AT_TILE + off);
    }

    float m0 = -1e30f, m1 = -1e30f, l0 = 0.f, l1 = 0.f;
    float O[8][4] = {};

    for (int cc = 0; cc < LVIS / 128; cc++) {
        // ---- S = Q K^T (16 n-tiles over s=128)
        float S[16][4] = {};
        const int lm = lane & 7, quad = lane >> 3;
#pragma unroll
        for (int nb = 0; nb < 4; nb++) {
#pragma unroll
            for (int ks = 0; ks < 4; ks++) {
                uint32_t bkh[2][4], bkl[2][4];
                const int brow = nb * 32 + ((quad & 2) ? 8 : 0) + lm;
                const int bcol = ks * 16 + (quad & 1) * 8;
#pragma unroll
                for (int np = 0; np < 2; np++) {
                    uint32_t off = ((brow + np * 16) * AT_STRIDE + bcol) * 2;
                    ldsm4(bkh[np], sb + 2 * AT_TILE + off);
                    ldsm4(bkl[np], sb + 3 * AT_TILE + off);
                }
#pragma unroll
                for (int ni = 0; ni < 4; ni++) {
                    float* acc = S[nb * 4 + ni];
                    const uint32_t* bhp = &bkh[ni >> 1][(ni & 1) * 2];
                    const uint32_t* blp = &bkl[ni >> 1][(ni & 1) * 2];
                    mma16816(acc, qh[ks], bhp);
                    mma16816(acc, qh[ks], blp);
                    mma16816(acc, ql[ks], bhp);
                }
            }
        }

        // ---- online softmax in fragments
        float mx0 = S[0][0], mx1 = S[0][2];
#pragma unroll
        for (int nt = 0; nt < 16; nt++) {
            mx0 = fmaxf(mx0, fmaxf(S[nt][0], S[nt][1]));
            mx1 = fmaxf(mx1, fmaxf(S[nt][2], S[nt][3]));
        }
        mx0 = fmaxf(mx0, __shfl_xor_sync(0xffffffffu, mx0, 1));
        mx0 = fmaxf(mx0, __shfl_xor_sync(0xffffffffu, mx0, 2));
        mx1 = fmaxf(mx1, __shfl_xor_sync(0xffffffffu, mx1, 1));
        mx1 = fmaxf(mx1, __shfl_xor_sync(0xffffffffu, mx1, 2));
        float mn0 = fmaxf(m0, mx0), mn1 = fmaxf(m1, mx1);
        float corr0 = __expf(m0 - mn0), corr1 = __expf(m1 - mn1);
        m0 = mn0; m1 = mn1;
        float rs0 = 0.f, rs1 = 0.f;
#pragma unroll
        for (int nt = 0; nt < 16; nt++) {
            S[nt][0] = __expf(S[nt][0] - m0); rs0 += S[nt][0];
            S[nt][1] = __expf(S[nt][1] - m0); rs0 += S[nt][1];
            S[nt][2] = __expf(S[nt][2] - m1); rs1 += S[nt][2];
            S[nt][3] = __expf(S[nt][3] - m1); rs1 += S[nt][3];
        }
        rs0 += __shfl_xor_sync(0xffffffffu, rs0, 1);
        rs0 += __shfl_xor_sync(0xffffffffu, rs0, 2);
        rs1 += __shfl_xor_sync(0xffffffffu, rs1, 1);
        rs1 += __shfl_xor_sync(0xffffffffu, rs1, 2);
        l0 = l0 * corr0 + rs0;
        l1 = l1 * corr1 + rs1;
#pragma unroll
        for (int nt = 0; nt < 8; nt++) {
            O[nt][0] *= corr0; O[nt][1] *= corr0;
            O[nt][2] *= corr1; O[nt][3] *= corr1;
        }

        // ---- O += P V (P split hi/lo in registers; V via trans ldmatrix)
#pragma unroll
        for (int ks2 = 0; ks2 < 8; ks2++) {
            float h00, h01, h10, h11, g00, g01, g10, g11;
            float e00 = bfres(S[2 * ks2][0], &h00), e01 = bfres(S[2 * ks2][1], &h01);
            float e10 = bfres(S[2 * ks2][2], &h10), e11 = bfres(S[2 * ks2][3], &h11);
            float f00 = bfres(S[2 * ks2 + 1][0], &g00), f01 = bfres(S[2 * ks2 + 1][1], &g01);
            float f10 = bfres(S[2 * ks2 + 1][2], &g10), f11 = bfres(S[2 * ks2 + 1][3], &g11);
            uint32_t pah[4] = {packbf(h00, h01), packbf(h10, h11),
                               packbf(g00, g01), packbf(g10, g11)};
            uint32_t pal[4] = {packbf(e00, e01), packbf(e10, e11),
                               packbf(f00, f01), packbf(f10, f11)};
            const int vrow = ks2 * 16 + ((lane >> 3) & 1) * 8 + (lane & 7);
#pragma unroll
            for (int nv = 0; nv < 4; nv++) {
                const int vcol = nv * 16 + (lane >> 4) * 8;
                uint32_t off = (vrow * AT_STRIDE + vcol) * 2;
                uint32_t bvh[4], bvl[4];
                ldsm4t(bvh, sb + 4 * AT_TILE + off);
                ldsm4t(bvl, sb + 5 * AT_TILE + off);
                mma16816(O[nv * 2], pah, &bvh[0]);
                mma16816(O[nv * 2], pah, &bvl[0]);
                mma16816(O[nv * 2], pal, &bvh[0]);
                mma16816(O[nv * 2 + 1], pah, &bvh[2]);
                mma16816(O[nv * 2 + 1], pah, &bvl[2]);
                mma16816(O[nv * 2 + 1], pal, &bvh[2]);
            }
        }

        __syncthreads();
        if (cc + 1 < LVIS / 128) {
            issue_kv(cc + 1);
            CP_COMMIT();
            CP_WAIT0();
            __syncthreads();
        }
    }

    // ---- write TGV (bf16 hi/lo) + stats
    const float inv0 = 1.f / l0, inv1 = 1.f / l1;
    const int r = lane >> 2, q = lane & 3;
    const int t0 = wid * 16 + r, t1 = t0 + 8;
#pragma unroll
    for (int nt = 0; nt < 8; nt++) {
        int col = nt * 8 + q * 2;
        float v00 = O[nt][0] * inv0, v01 = O[nt][1] * inv0;
        float v10 = O[nt][2] * inv1, v11 = O[nt][3] * inv1;
        float h00, h01, h10, h11;
        float l00 = bfres(v00, &h00), l01 = bfres(v01, &h01);
        float l10 = bfres(v10, &h10), l11 = bfres(v11, &h11);
        *(uint32_t*)&g_TGVh[((size_t)bh * 128 + t0) * 64 + col] = packbf(h00, h01);
        *(uint32_t*)&g_TGVh[((size_t)bh * 128 + t1) * 64 + col] = packbf(h10, h11);
        *(uint32_t*)&g_TGVl[((size_t)bh * 128 + t0) * 64 + col] = packbf(l00, l01);
        *(uint32_t*)&g_TGVl[((size_t)bh * 128 + t1) * 64 + col] = packbf(l10, l11);
    }
    if (q == 0) {
        g_M[bh * 128 + t0] = m0; g_M[bh * 128 + t1] = m1;
        g_L[bh * 128 + t0] = l0; g_L[bh * 128 + t1] = l1;
    }
}

// ---------------- attention pass 2 on mma.sync ------------------------------------
// grid (32 s-chunks, 256 bh). AO written into g_Kh/g_Kl (bf16 hi/lo).
#define P2_SMEM (6 * AT_TILE + 1024)

__global__ void __launch_bounds__(256, 2)
attn2_mma()
{
    extern __shared__ __align__(256) char smem[];
    const uint32_t sb = smem_u32(smem);
    float* m_s = (float*)(smem + 6 * AT_TILE);
    float* rl_s = m_s + 128;
    const int tid = threadIdx.x;
    const int wid = tid >> 5, lane = tid & 31;
    const int cc = blockIdx.x, bh = blockIdx.y, b = bh >> 4, h = bh & 15;
    const size_t row0 = (size_t)b * LVIS + cc * 128;

    // loads: Q(2 tiles), Kchunk(2), TGV(2) = 6144 segs
#pragma unroll
    for (int i = 0; i < 24; i++) {
        int q = tid + i * 256;
        int tile = q >> 10, rem = q & 1023, r = rem >> 3, s = rem & 7;
        const __nv_bfloat16* src;
        if (tile == 0)      src = g_Qh + (size_t)(b * LTEXT + r) * DD + h * HD + s * 8;
        else if (tile == 1) src = g_Ql + (size_t)(b * LTEXT + r) * DD + h * HD + s * 8;
        else if (tile == 2) src = g_Kh + (row0 + r) * DD + h * HD + s * 8;
        else if (tile == 3) src = g_Kl + (row0 + r) * DD + h * HD + s * 8;
        else if (tile == 4) src = g_TGVh + ((size_t)bh * 128 + r) * 64 + s * 8;
        else                src = g_TGVl + ((size_t)bh * 128 + r) * 64 + s * 8;
        cp_async16(sb + tile * AT_TILE + r * (AT_STRIDE * 2) + s * 16, src);
    }
    CP_COMMIT();
    if (tid < 128) {
        m_s[tid] = g_M[bh * 128 + tid];
        rl_s[tid] = 1.f / g_L[bh * 128 + tid];
    }
    CP_WAIT0();
    __syncthreads();

    // A fragments: K rows (this warp's 16 s-rows), hi & lo
    uint32_t kh[4][4], kl[4][4];
#pragma unroll
    for (int ks = 0; ks < 4; ks++) {
        uint32_t off = ((wid * 16 + (lane & 15)) * AT_STRIDE + ks * 16 + (lane >> 4) * 8) * 2;
        ldsm4(kh[ks], sb + 2 * AT_TILE + off);
        ldsm4(kl[ks], sb + 3 * AT_TILE + off);
    }

    // S^T = K Q^T
    float S[16][4] = {};
    const int lm = lane & 7, quad = lane >> 3;
#pragma unroll
    for (int nb = 0; nb < 4; nb++) {
#pragma unroll
        for (int ks = 0; ks < 4; ks++) {
            uint32_t bqh[2][4], bql[2][4];
            const int brow = nb * 32 + ((quad & 2) ? 8 : 0) + lm;
            const int bcol = ks * 16 + (quad & 1) * 8;
#pragma unroll
            for (int np = 0; np < 2; np++) {
                uint32_t off = ((brow + np * 16) * AT_STRIDE + bcol) * 2;
                ldsm4(bqh[np], sb + off);
                ldsm4(bql[np], sb + AT_TILE + off);
            }
#pragma unroll
            for (int ni = 0; ni < 4; ni++) {
                float* acc = S[nb * 4 + ni];
                const uint32_t* bhp = &bqh[ni >> 1][(ni & 1) * 2];
                const uint32_t* blp = &bql[ni >> 1][(ni & 1) * 2];
                mma16816(acc, kh[ks], bhp);
                mma16816(acc, kh[ks], blp);
                mma16816(acc, kl[ks], bhp);
            }
        }
    }

    // P^T[s][t] = exp(S^T - m[t]) / l[t]
    const int q = lane & 3;
#pragma unroll
    for (int nt = 0; nt < 16; nt++) {
        int c0 = nt * 8 + q * 2;
        float mm0 = m_s[c0], mm1 = m_s[c0 + 1];
        float rr0 = rl_s[c0], rr1 = rl_s[c0 + 1];
        S[nt][0] = __expf(S[nt][0] - mm0) * rr0;
        S[nt][1] = __expf(S[nt][1] - mm1) * rr1;
        S[nt][2] = __expf(S[nt][2] - mm0) * rr0;
        S[nt][3] = __expf(S[nt][3] - mm1) * rr1;
    }

    // O = P^T TGV
    float O[8][4] = {};
#pragma unroll
    for (int ks2 = 0; ks2 < 8; ks2++) {
        float h00, h01, h10, h11, g00, g01, g10, g11;
        float e00 = bfres(S[2 * ks2][0], &h00), e01 = bfres(S[2 * ks2][1], &h01);
        float e10 = bfres(S[2 * ks2][2], &h10), e11 = bfres(S[2 * ks2][3], &h11);
        float f00 = bfres(S[2 * ks2 + 1][0], &g00), f01 = bfres(S[2 * ks2 + 1][1], &g01);
        float f10 = bfres(S[2 * ks2 + 1][2], &g10), f11 = bfres(S[2 * ks2 + 1][3], &g11);
        uint32_t pah[4] = {packbf(h00, h01), packbf(h10, h11),
                           packbf(g00, g01), packbf(g10, g11)};
        uint32_t pal[4] = {packbf(e00, e01), packbf(e10, e11),
                           packbf(f00, f01), packbf(f10, f11)};
        const int vrow = ks2 * 16 + ((lane >> 3) & 1) * 8 + (lane & 7);
#pragma unroll
        for (int nv = 0; nv < 4; nv++) {
            const int vcol = nv * 16 + (lane >> 4) * 8;
            uint32_t off = (vrow * AT_STRIDE + vcol) * 2;
            uint32_t bvh[4], bvl[4];
            ldsm4t(bvh, sb + 4 * AT_TILE + off);
            ldsm4t(bvl, sb + 5 * AT_TILE + off);
            mma16816(O[nv * 2], pah, &bvh[0]);
            mma16816(O[nv * 2], pah, &bvl[0]);
            mma16816(O[nv * 2], pal, &bvh[0]);
            mma16816(O[nv * 2 + 1], pah, &bvh[2]);
            mma16816(O[nv * 2 + 1], pah, &bvl[2]);
            mma16816(O[nv * 2 + 1], pal, &bvh[2]);
        }
    }

    // write AO (bf16 hi/lo) into g_Kh/g_Kl — this block is the unique owner of
    // rows [row0+wid*16 ..] x cols [h*64 ..+63].
    const int r = lane >> 2;
    const size_t s0r = row0 + wid * 16 + r;
#pragma unroll
    for (int nt = 0; nt < 8; nt++) {
        int col = h * HD + nt * 8 + q * 2;
        float h00, h01, h10, h11;
        float l00 = bfres(O[nt][0], &h00), l01 = bfres(O[nt][1], &h01);
        float l10 = bfres(O[nt][2], &h10), l11 = bfres(O[nt][3], &h11);
        *(uint32_t*)&g_Kh[s0r * DD + col] = packbf(h00, h01);
        *(uint32_t*)&g_Kh[(s0r + 8) * DD + col] = packbf(h10, h11);
        *(uint32_t*)&g_Kl[s0r * DD + col] = packbf(l00, l01);
        *(uint32_t*)&g_Kl[(s0r + 8) * DD + col] = packbf(l10, l11);
    }
}

// ---------------- launch ----------------------------------------------------------
extern "C" void kernel_launch(void* const* d_in, const int* in_sizes, int n_in,
                              void* d_out, int out_size)
{
    const float* hidden = nullptr;
    const float* text = nullptr;
    const float* Ws[4] = {nullptr, nullptr, nullptr, nullptr};
    const float* bs[4] = {nullptr, nullptr, nullptr, nullptr};
    int nw = 0, nb = 0;
    for (int i = 0; i < n_in; i++) {
        int sz = in_sizes[i];
        const float* p = (const float*)d_in[i];
        if (sz == BB * LVIS * DD) { if (!hidden) hidden = p; }
        else if (sz == LTEXT * BB * DD) { if (!text) text = p; }
        else if (sz == DD * DD) { if (nw < 4) Ws[nw++] = p; }
        else if (sz == DD) { if (nb < 4) bs[nb++] = p; }
    }
    if (!hidden) hidden = (const float*)d_in[0];
    if (!text) text = (const float*)d_in[1];
    if (nw < 4) { Ws[0]=(const float*)d_in[2]; Ws[1]=(const float*)d_in[4];
                  Ws[2]=(const float*)d_in[6]; Ws[3]=(const float*)d_in[8]; }
    if (nb < 4) { bs[0]=(const float*)d_in[3]; bs[1]=(const float*)d_in[5];
                  bs[2]=(const float*)d_in[7]; bs[3]=(const float*)d_in[9]; }
    float* out = (float*)d_out;

    cudaFuncSetAttribute(gemm_mma, cudaFuncAttributeMaxDynamicSharedMemorySize, G_SMEM);
    cudaFuncSetAttribute(attn1_mma, cudaFuncAttributeMaxDynamicSharedMemorySize, P1_SMEM);
    cudaFuncSetAttribute(attn2_mma, cudaFuncAttributeMaxDynamicSharedMemorySize, P2_SMEM);

    for (int w = 0; w < 4; w++)
        convert_wt<<<dim3(32, 32), dim3(32, 8)>>>(Ws[w], w);
    convert_split<<<2048, 256>>>(text, 0, (size_t)LTEXT * BB * DD / 4);
    convert_split<<<8192, 256>>>(hidden, 1, (size_t)BB * LVIS * DD / 4);

    gemm_mma<<<dim3(8, 16), 256, G_SMEM>>>(0, 0, bs[0], nullptr, 1, 0.125f);   // Q
    gemm_mma<<<dim3(8, 512), 256, G_SMEM>>>(1, 1, bs[1], nullptr, 2, 1.f);     // K
    gemm_mma<<<dim3(8, 512), 256, G_SMEM>>>(1, 2, bs[2], nullptr, 3, 1.f);     // V

    attn1_mma<<<BB * HH, 256, P1_SMEM>>>();
    attn2_mma<<<dim3(LVIS / 128, BB * HH), 256, P2_SMEM>>>();

    gemm_mma<<<dim3(8, 512), 256, G_SMEM>>>(2, 3, bs[3], out, 0, 1.f);         // O
}

// round 8
// speedup vs baseline: 3.1626x; 1.4833x over previous
#include <cuda_runtime.h>
#include <cstdint>
#include <cstddef>

#define BB 16
#define LTEXT 128
#define LVIS 4096
#define DD 1024
#define HH 16
#define HD 64

// ---------------- scratch (fp32, tf32-rounded in place) ---------------------------
__device__ __align__(256) float g_A[(size_t)BB * LVIS * DD];   // hidden rounded 268MB
__device__ __align__(256) float g_T[BB * LTEXT * DD];          // text rounded 8MB
__device__ __align__(256) float g_W[4 * DD * DD];              // W^T (N,K) rounded
__device__ __align__(256) float g_Q[BB * LTEXT * DD];          // Q (scaled, rounded)
__device__ __align__(256) float g_K[(size_t)BB * LVIS * DD];   // K, later AO (rounded)
__device__ __align__(256) float g_Vt[(size_t)BB * HH * HD * LVIS];  // V^T per head
__device__ __align__(256) float g_TGVt[BB * HH * HD * LTEXT];  // TGV^T per head
__device__ __align__(256) float g_M[BB * HH * LTEXT];
__device__ __align__(256) float g_L[BB * HH * LTEXT];

// ---------------- helpers --------------------------------------------------------
__device__ __forceinline__ uint32_t smem_u32(const void* p) {
    uint32_t a;
    asm("{ .reg .u64 t; cvta.to.shared.u64 t, %1; cvt.u32.u64 %0, t; }" : "=r"(a) : "l"(p));
    return a;
}
__device__ __forceinline__ uint32_t cvt_tf32(float x) {
    uint32_t u;
    asm("cvt.rna.tf32.f32 %0, %1;" : "=r"(u) : "f"(x));
    return u;
}
__device__ __forceinline__ float rtf(float x) { return __uint_as_float(cvt_tf32(x)); }

__device__ __forceinline__ void ldsm4(uint32_t* r, uint32_t addr) {
    asm volatile("ldmatrix.sync.aligned.m8n8.x4.shared.b16 {%0,%1,%2,%3}, [%4];"
                 : "=r"(r[0]), "=r"(r[1]), "=r"(r[2]), "=r"(r[3]) : "r"(addr));
}
__device__ __forceinline__ void mma_tf32(float* d, const uint32_t* a, const uint32_t* b) {
    asm volatile("mma.sync.aligned.m16n8k8.row.col.f32.tf32.tf32.f32 "
                 "{%0,%1,%2,%3}, {%4,%5,%6,%7}, {%8,%9}, {%0,%1,%2,%3};"
                 : "+f"(d[0]), "+f"(d[1]), "+f"(d[2]), "+f"(d[3])
                 : "r"(a[0]), "r"(a[1]), "r"(a[2]), "r"(a[3]), "r"(b[0]), "r"(b[1]));
}
__device__ __forceinline__ void cp_async16(uint32_t dst, const void* src) {
    asm volatile("cp.async.cg.shared.global [%0], [%1], 16;" :: "r"(dst), "l"(src));
}
#define CP_COMMIT() asm volatile("cp.async.commit_group;" ::: "memory")
#define CP_WAIT0() asm volatile("cp.async.wait_group 0;" ::: "memory")

// P (fp32 in accum frags) -> tf32 A-fragment for one k8 slice, via quad shuffles.
__device__ __forceinline__ void pfrag(const float* s4, uint32_t* a, int lane) {
    int srcA = (lane & ~3) | ((lane & 3) >> 1);
    int srcB = srcA + 2;
    bool odd = lane & 1;
    float x0 = __shfl_sync(0xffffffffu, s4[0], srcA);
    float x1 = __shfl_sync(0xffffffffu, s4[1], srcA);
    float x2 = __shfl_sync(0xffffffffu, s4[2], srcA);
    float x3 = __shfl_sync(0xffffffffu, s4[3], srcA);
    float y0 = __shfl_sync(0xffffffffu, s4[0], srcB);
    float y1 = __shfl_sync(0xffffffffu, s4[1], srcB);
    float y2 = __shfl_sync(0xffffffffu, s4[2], srcB);
    float y3 = __shfl_sync(0xffffffffu, s4[3], srcB);
    a[0] = cvt_tf32(odd ? x1 : x0);
    a[1] = cvt_tf32(odd ? x3 : x2);
    a[2] = cvt_tf32(odd ? y1 : y0);
    a[3] = cvt_tf32(odd ? y3 : y2);
}

// ---------------- conversion kernels ---------------------------------------------
__global__ void round_copy(const float* __restrict__ src, int dst_sel, size_t n4)
{
    float* dst = dst_sel ? g_A : g_T;
    size_t stride = (size_t)gridDim.x * blockDim.x;
    for (size_t i = (size_t)blockIdx.x * blockDim.x + threadIdx.x; i < n4; i += stride) {
        float4 v = ((const float4*)src)[i];
        v.x = rtf(v.x); v.y = rtf(v.y); v.z = rtf(v.z); v.w = rtf(v.w);
        ((float4*)dst)[i] = v;
    }
}

__global__ void convert_wt(const float* __restrict__ W, int widx)
{
    __shared__ float t[32][33];
    int tx = threadIdx.x, ty = threadIdx.y;   // (32,8)
    int n = blockIdx.x * 32 + tx;
    int k0 = blockIdx.y * 32;
#pragma unroll
    for (int j = 0; j < 32; j += 8)
        t[ty + j][tx] = W[(size_t)(k0 + ty + j) * DD + n];
    __syncthreads();
    float* wt = g_W + (size_t)widx * DD * DD;
    int k = k0 + tx;
    int nn0 = blockIdx.x * 32;
#pragma unroll
    for (int j = 0; j < 32; j += 8)
        wt[(size_t)(nn0 + ty + j) * DD + k] = rtf(t[tx][ty + j]);
}

// ---------------- tf32 GEMM on mma.sync -------------------------------------------
// C[M,1024] = alpha*(A@W^T + bias). A fp32 [M,K] rounded; W^T fp32 (N,K) rounded.
// 128x128 tile, BK=32, 8 warps (2m x 4n), warp 64x32, m16n8k8.
#define GP 36                       // f32 row stride (conflict-free ldsm)
#define GTILE (128 * GP * 4)        // 18432 B
#define GSTAGE (2 * GTILE)
#define G_SMEM (2 * GSTAGE)         // 73728 B

__global__ void __launch_bounds__(256)
gemm_tf32(int a_sel, int w_idx, const float* __restrict__ bias, float* __restrict__ Cx,
          int c_mode, float alpha)
{
    extern __shared__ __align__(256) char smem[];
    const uint32_t sb = smem_u32(smem);
    const int tid = threadIdx.x;
    const int wid = tid >> 5, lane = tid & 31;
    const int warp_m = wid & 1, warp_n = wid >> 1;

    const float* A = (a_sel == 0) ? g_T : (a_sel == 1) ? g_A : g_K;
    const float* B = g_W + (size_t)w_idx * DD * DD;

    const int n0 = blockIdx.x * 128;
    const size_t m0 = (size_t)blockIdx.y * 128;

    float acc[4][4][4] = {};

    auto issue = [&](int kt, int stage) {
        const int k0 = kt * 32;
        const uint32_t sdst = sb + stage * GSTAGE;
#pragma unroll
        for (int i = 0; i < 8; i++) {
            int q = tid + i * 256;
            int tile = q >> 10, rem = q & 1023, r = rem >> 3, seg = rem & 7;
            const float* src = tile ? B + (size_t)(n0 + r) * DD + k0 + seg * 4
                                    : A + (m0 + r) * DD + k0 + seg * 4;
            cp_async16(sdst + tile * GTILE + (r * GP + seg * 4) * 4, src);
        }
        CP_COMMIT();
    };

    issue(0, 0);
    for (int kt = 0; kt < 32; kt++) {
        if (kt + 1 < 32) {
            issue(kt + 1, (kt + 1) & 1);
            asm volatile("cp.async.wait_group 1;" ::: "memory");
        } else {
            CP_WAIT0();
        }
        __syncthreads();

        const uint32_t so = sb + (kt & 1) * GSTAGE;
#pragma unroll
        for (int ks = 0; ks < 4; ks++) {
            uint32_t af[4][4], bf[2][4];
#pragma unroll
            for (int mi = 0; mi < 4; mi++) {
                uint32_t addr = so + ((warp_m * 64 + mi * 16 + (lane & 7) +
                                       ((lane >> 3) & 1) * 8) * GP +
                                      ks * 8 + (lane >> 4) * 4) * 4;
                ldsm4(af[mi], addr);
            }
#pragma unroll
            for (int pr = 0; pr < 2; pr++) {
                uint32_t addr = so + GTILE + ((warp_n * 32 + pr * 16 + (lane & 7) +
                                               ((lane >> 4) & 1) * 8) * GP +
                                              ks * 8 + ((lane >> 3) & 1) * 4) * 4;
                ldsm4(bf[pr], addr);
            }
#pragma unroll
            for (int mi = 0; mi < 4; mi++)
#pragma unroll
                for (int ni = 0; ni < 4; ni++)
                    mma_tf32(acc[mi][ni], af[mi], &bf[ni >> 1][(ni & 1) * 2]);
        }
        __syncthreads();
    }

    // epilogue
#pragma unroll
    for (int ni = 0; ni < 4; ni++) {
        const int col = n0 + warp_n * 32 + ni * 8 + (lane & 3) * 2;
        const float b0 = bias[col], b1 = bias[col + 1];
#pragma unroll
        for (int mi = 0; mi < 4; mi++) {
            const size_t r0 = m0 + warp_m * 64 + mi * 16 + (lane >> 2);
            float v00 = alpha * (acc[mi][ni][0] + b0);
            float v01 = alpha * (acc[mi][ni][1] + b1);
            float v10 = alpha * (acc[mi][ni][2] + b0);
            float v11 = alpha * (acc[mi][ni][3] + b1);
            if (c_mode == 0) {
                *(float2*)&Cx[r0 * DD + col] = {v00, v01};
                *(float2*)&Cx[(r0 + 8) * DD + col] = {v10, v11};
            } else if (c_mode == 3) {
                // V^T per head: g_Vt[(b*16+h)*64 + d][s]
                int b_ = (int)(m0 >> 12);
                int sr = (int)(m0 & 4095) + warp_m * 64 + mi * 16 + (lane >> 2);
                int hh = col >> 6, dd0 = col & 63;
                size_t base0 = ((size_t)(b_ * 16 + hh) * 64 + dd0) * (size_t)LVIS;
                g_Vt[base0 + sr] = rtf(v00);
                g_Vt[base0 + LVIS + sr] = rtf(v01);
                g_Vt[base0 + sr + 8] = rtf(v10);
                g_Vt[base0 + LVIS + sr + 8] = rtf(v11);
            } else {
                float* C = (c_mode == 1) ? g_Q : g_K;
                *(float2*)&C[r0 * DD + col] = {rtf(v00), rtf(v01)};
                *(float2*)&C[(r0 + 8) * DD + col] = {rtf(v10), rtf(v11)};
            }
        }
    }
}

// ---------------- attention pass 1 (tf32 flash) -----------------------------------
#define QP 68                        // f32 stride for [row][64] tiles
#define QTILE (128 * QP * 4)         // 34816 B
#define VP 132                       // f32 stride for [64][128] V^T tile
#define VTILE (64 * VP * 4)          // 33792 B
#define OFF_K1 QTILE
#define OFF_V1 (2 * QTILE)
#define P1_SMEM (2 * QTILE + VTILE)  // 103424 B

__global__ void __launch_bounds__(256, 2)
attn1_tf32()
{
    extern __shared__ __align__(256) char smem[];
    const uint32_t sb = smem_u32(smem);
    const int tid = threadIdx.x;
    const int wid = tid >> 5, lane = tid & 31;
    const int bh = blockIdx.x, b = bh >> 4, h = bh & 15;

    // Q tile load
#pragma unroll
    for (int i = 0; i < 8; i++) {
        int q = tid + i * 256;
        int r = q >> 4, seg = q & 15;
        cp_async16(sb + (r * QP + seg * 4) * 4,
                   g_Q + (size_t)(b * LTEXT + r) * DD + h * HD + seg * 4);
    }

    auto issue_kv = [&](int cc) {
        const size_t row0 = (size_t)b * LVIS + cc * 128;
        const float* vt = g_Vt + ((size_t)bh * 64) * LVIS + cc * 128;
#pragma unroll
        for (int i = 0; i < 16; i++) {
            int q = tid + i * 256;
            int tile = q >> 11, rem = q & 2047;
            if (tile == 0) {
                int r = rem >> 4, seg = rem & 15;
                cp_async16(sb + OFF_K1 + (r * QP + seg * 4) * 4,
                           g_K + (row0 + r) * DD + h * HD + seg * 4);
            } else {
                int r = rem >> 5, seg = rem & 31;
                cp_async16(sb + OFF_V1 + (r * VP + seg * 4) * 4,
                           vt + (size_t)r * LVIS + seg * 4);
            }
        }
    };

    issue_kv(0);
    CP_COMMIT();
    CP_WAIT0();
    __syncthreads();

    // preload Q fragments: 8 k8 steps over d=64
    uint32_t qf[8][4];
#pragma unroll
    for (int ks = 0; ks < 8; ks++) {
        uint32_t addr = sb + ((wid * 16 + (lane & 7) + ((lane >> 3) & 1) * 8) * QP +
                              ks * 8 + (lane >> 4) * 4) * 4;
        ldsm4(qf[ks], addr);
    }

    float m0 = -1e30f, m1 = -1e30f, l0 = 0.f, l1 = 0.f;
    float O[8][4] = {};

    for (int cc = 0; cc < LVIS / 128; cc++) {
        // ---- S = Q K^T
        float S[16][4] = {};
#pragma unroll
        for (int ks = 0; ks < 8; ks++) {
#pragma unroll
            for (int pr = 0; pr < 8; pr++) {
                uint32_t bf[4];
                uint32_t addr = sb + OFF_K1 +
                    ((pr * 16 + (lane & 7) + ((lane >> 4) & 1) * 8) * QP +
                     ks * 8 + ((lane >> 3) & 1) * 4) * 4;
                ldsm4(bf, addr);
                mma_tf32(S[pr * 2], qf[ks], &bf[0]);
                mma_tf32(S[pr * 2 + 1], qf[ks], &bf[2]);
            }
        }

        // ---- online softmax
        float mx0 = S[0][0], mx1 = S[0][2];
#pragma unroll
        for (int nt = 0; nt < 16; nt++) {
            mx0 = fmaxf(mx0, fmaxf(S[nt][0], S[nt][1]));
            mx1 = fmaxf(mx1, fmaxf(S[nt][2], S[nt][3]));
        }
        mx0 = fmaxf(mx0, __shfl_xor_sync(0xffffffffu, mx0, 1));
        mx0 = fmaxf(mx0, __shfl_xor_sync(0xffffffffu, mx0, 2));
        mx1 = fmaxf(mx1, __shfl_xor_sync(0xffffffffu, mx1, 1));
        mx1 = fmaxf(mx1, __shfl_xor_sync(0xffffffffu, mx1, 2));
        float mn0 = fmaxf(m0, mx0), mn1 = fmaxf(m1, mx1);
        float corr0 = __expf(m0 - mn0), corr1 = __expf(m1 - mn1);
        m0 = mn0; m1 = mn1;
        float rs0 = 0.f, rs1 = 0.f;
#pragma unroll
        for (int nt = 0; nt < 16; nt++) {
            S[nt][0] = __expf(S[nt][0] - m0); rs0 += S[nt][0];
            S[nt][1] = __expf(S[nt][1] - m0); rs0 += S[nt][1];
            S[nt][2] = __expf(S[nt][2] - m1); rs1 += S[nt][2];
            S[nt][3] = __expf(S[nt][3] - m1); rs1 += S[nt][3];
        }
        rs0 += __shfl_xor_sync(0xffffffffu, rs0, 1);
        rs0 += __shfl_xor_sync(0xffffffffu, rs0, 2);
        rs1 += __shfl_xor_sync(0xffffffffu, rs1, 1);
        rs1 += __shfl_xor_sync(0xffffffffu, rs1, 2);
        l0 = l0 * corr0 + rs0;
        l1 = l1 * corr1 + rs1;
#pragma unroll
        for (int nt = 0; nt < 8; nt++) {
            O[nt][0] *= corr0; O[nt][1] *= corr0;
            O[nt][2] *= corr1; O[nt][3] *= corr1;
        }

        // ---- O += P V  (P via shuffles; V^T tile as B operand)
#pragma unroll
        for (int kt = 0; kt < 16; kt++) {
            uint32_t pa[4];
            pfrag(S[kt], pa, lane);
#pragma unroll
            for (int dp = 0; dp < 4; dp++) {
                uint32_t bf[4];
                uint32_t addr = sb + OFF_V1 +
                    ((dp * 16 + (lane & 7) + ((lane >> 4) & 1) * 8) * VP +
                     kt * 8 + ((lane >> 3) & 1) * 4) * 4;
                ldsm4(bf, addr);
                mma_tf32(O[dp * 2], pa, &bf[0]);
                mma_tf32(O[dp * 2 + 1], pa, &bf[2]);
            }
        }

        __syncthreads();
        if (cc + 1 < LVIS / 128) {
            issue_kv(cc + 1);
            CP_COMMIT();
            CP_WAIT0();
            __syncthreads();
        }
    }

    // ---- write TGV^T (rounded) + stats
    const float inv0 = 1.f / l0, inv1 = 1.f / l1;
    const int r = lane >> 2, q = lane & 3;
    const int t0 = wid * 16 + r, t1 = t0 + 8;
#pragma unroll
    for (int nt = 0; nt < 8; nt++) {
        int d0 = nt * 8 + q * 2;
        float* tg = g_TGVt + ((size_t)bh * 64 + d0) * LTEXT;
        tg[t0] = rtf(O[nt][0] * inv0);
        tg[t1] = rtf(O[nt][2] * inv1);
        tg[LTEXT + t0] = rtf(O[nt][1] * inv0);
        tg[LTEXT + t1] = rtf(O[nt][3] * inv1);
    }
    if (q == 0) {
        g_M[bh * 128 + t0] = m0; g_M[bh * 128 + t1] = m1;
        g_L[bh * 128 + t0] = l0; g_L[bh * 128 + t1] = l1;
    }
}

// ---------------- attention pass 2 (tf32) -----------------------------------------
#define OFF_K2 QTILE
#define OFF_T2 (2 * QTILE)
#define P2_SMEM (2 * QTILE + VTILE + 1024)

__global__ void __launch_bounds__(256, 2)
attn2_tf32()
{
    extern __shared__ __align__(256) char smem[];
    const uint32_t sb = smem_u32(smem);
    float* m_s = (float*)(smem + 2 * QTILE + VTILE);
    float* rl_s = m_s + 128;
    const int tid = threadIdx.x;
    const int wid = tid >> 5, lane = tid & 31;
    const int cc = blockIdx.x, bh = blockIdx.y, b = bh >> 4, h = bh & 15;
    const size_t row0 = (size_t)b * LVIS + cc * 128;

#pragma unroll
    for (int i = 0; i < 24; i++) {
        int q = tid + i * 256;
        int tile = q >> 11, rem = q & 2047;
        if (tile == 0) {
            int r = rem >> 4, seg = rem & 15;
            cp_async16(sb + (r * QP + seg * 4) * 4,
                       g_Q + (size_t)(b * LTEXT + r) * DD + h * HD + seg * 4);
        } else if (tile == 1) {
            int r = rem >> 4, seg = rem & 15;
            cp_async16(sb + OFF_K2 + (r * QP + seg * 4) * 4,
                       g_K + (row0 + r) * DD + h * HD + seg * 4);
        } else {
            int r = rem >> 5, seg = rem & 31;
            cp_async16(sb + OFF_T2 + (r * VP + seg * 4) * 4,
                       g_TGVt + ((size_t)bh * 64 + r) * LTEXT + seg * 4);
        }
    }
    CP_COMMIT();
    if (tid < 128) {
        m_s[tid] = g_M[bh * 128 + tid];
        rl_s[tid] = 1.f / g_L[bh * 128 + tid];
    }
    CP_WAIT0();
    __syncthreads();

    // preload K fragments (A operand: this warp's 16 s-rows)
    uint32_t kf[8][4];
#pragma unroll
    for (int ks = 0; ks < 8; ks++) {
        uint32_t addr = sb + OFF_K2 + ((wid * 16 + (lane & 7) + ((lane >> 3) & 1) * 8) * QP +
                                       ks * 8 + (lane >> 4) * 4) * 4;
        ldsm4(kf[ks], addr);
    }

    // S^T = K Q^T
    float S[16][4] = {};
#pragma unroll
    for (int ks = 0; ks < 8; ks++) {
#pragma unroll
        for (int pr = 0; pr < 8; pr++) {
            uint32_t bf[4];
            uint32_t addr = sb + ((pr * 16 + (lane & 7) + ((lane >> 4) & 1) * 8) * QP +
                                  ks * 8 + ((lane >> 3) & 1) * 4) * 4;
            ldsm4(bf, addr);
            mma_tf32(S[pr * 2], kf[ks], &bf[0]);
            mma_tf32(S[pr * 2 + 1], kf[ks], &bf[2]);
        }
    }

    // P^T = exp(S^T - m[t]) / l[t]
    const int q = lane & 3;
#pragma unroll
    for (int nt = 0; nt < 16; nt++) {
        int c0 = nt * 8 + q * 2;
        S[nt][0] = __expf(S[nt][0] - m_s[c0]) * rl_s[c0];
        S[nt][1] = __expf(S[nt][1] - m_s[c0 + 1]) * rl_s[c0 + 1];
        S[nt][2] = __expf(S[nt][2] - m_s[c0]) * rl_s[c0];
        S[nt][3] = __expf(S[nt][3] - m_s[c0 + 1]) * rl_s[c0 + 1];
    }

    // O = P^T TGV (TGV^T tile as B operand)
    float O[8][4] = {};
#pragma unroll
    for (int kt = 0; kt < 16; kt++) {
        uint32_t pa[4];
        pfrag(S[kt], pa, lane);
#pragma unroll
        for (int dp = 0; dp < 4; dp++) {
            uint32_t bf[4];
            uint32_t addr = sb + OFF_T2 +
                ((dp * 16 + (lane & 7) + ((lane >> 4) & 1) * 8) * VP +
                 kt * 8 + ((lane >> 3) & 1) * 4) * 4;
            ldsm4(bf, addr);
            mma_tf32(O[dp * 2], pa, &bf[0]);
            mma_tf32(O[dp * 2 + 1], pa, &bf[2]);
        }
    }

    // write AO (rounded) into g_K
    const int r = lane >> 2;
    const size_t s0r = row0 + wid * 16 + r;
#pragma unroll
    for (int nt = 0; nt < 8; nt++) {
        int col = h * HD + nt * 8 + q * 2;
        *(float2*)&g_K[s0r * DD + col] = {rtf(O[nt][0]), rtf(O[nt][1])};
        *(float2*)&g_K[(s0r + 8) * DD + col] = {rtf(O[nt][2]), rtf(O[nt][3])};
    }
}

// ---------------- launch ----------------------------------------------------------
extern "C" void kernel_launch(void* const* d_in, const int* in_sizes, int n_in,
                              void* d_out, int out_size)
{
    const float* hidden = nullptr;
    const float* text = nullptr;
    const float* Ws[4] = {nullptr, nullptr, nullptr, nullptr};
    const float* bs[4] = {nullptr, nullptr, nullptr, nullptr};
    int nw = 0, nb = 0;
    for (int i = 0; i < n_in; i++) {
        int sz = in_sizes[i];
        const float* p = (const float*)d_in[i];
        if (sz == BB * LVIS * DD) { if (!hidden) hidden = p; }
        else if (sz == LTEXT * BB * DD) { if (!text) text = p; }
        else if (sz == DD * DD) { if (nw < 4) Ws[nw++] = p; }
        else if (sz == DD) { if (nb < 4) bs[nb++] = p; }
    }
    if (!hidden) hidden = (const float*)d_in[0];
    if (!text) text = (const float*)d_in[1];
    if (nw < 4) { Ws[0]=(const float*)d_in[2]; Ws[1]=(const float*)d_in[4];
                  Ws[2]=(const float*)d_in[6]; Ws[3]=(const float*)d_in[8]; }
    if (nb < 4) { bs[0]=(const float*)d_in[3]; bs[1]=(const float*)d_in[5];
                  bs[2]=(const float*)d_in[7]; bs[3]=(const float*)d_in[9]; }
    float* out = (float*)d_out;

    cudaFuncSetAttribute(gemm_tf32, cudaFuncAttributeMaxDynamicSharedMemorySize, G_SMEM);
    cudaFuncSetAttribute(attn1_tf32, cudaFuncAttributeMaxDynamicSharedMemorySize, P1_SMEM);
    cudaFuncSetAttribute(attn2_tf32, cudaFuncAttributeMaxDynamicSharedMemorySize, P2_SMEM);

    for (int w = 0; w < 4; w++)
        convert_wt<<<dim3(32, 32), dim3(32, 8)>>>(Ws[w], w);
    round_copy<<<2048, 256>>>(text, 0, (size_t)LTEXT * BB * DD / 4);
    round_copy<<<8192, 256>>>(hidden, 1, (size_t)BB * LVIS * DD / 4);

    gemm_tf32<<<dim3(8, 16), 256, G_SMEM>>>(0, 0, bs[0], nullptr, 1, 0.125f);   // Q
    gemm_tf32<<<dim3(8, 512), 256, G_SMEM>>>(1, 1, bs[1], nullptr, 2, 1.f);     // K
    gemm_tf32<<<dim3(8, 512), 256, G_SMEM>>>(1, 2, bs[2], nullptr, 3, 1.f);     // V^T

    attn1_tf32<<<BB * HH, 256, P1_SMEM>>>();
    attn2_tf32<<<dim3(LVIS / 128, BB * HH), 256, P2_SMEM>>>();

    gemm_tf32<<<dim3(8, 512), 256, G_SMEM>>>(2, 3, bs[3], out, 0, 1.f);         // O
}

// round 11
// speedup vs baseline: 5.0185x; 1.5868x over previous
#include <cuda_runtime.h>
#include <cuda_fp16.h>
#include <cstdint>
#include <cstddef>

#define BB 16
#define LTEXT 128
#define LVIS 4096
#define DD 1024
#define HH 16
#define HD 64

// ---------------- scratch (fp16 interchange) --------------------------------------
__device__ __align__(256) __half g_A[(size_t)BB * LVIS * DD];   // hidden fp16 134MB
__device__ __align__(256) __half g_T[BB * LTEXT * DD];          // text fp16 4MB
__device__ __align__(256) __half g_W[4 * DD * DD];              // W^T (N,K) fp16 8MB
__device__ __align__(256) __half g_Q[BB * LTEXT * DD];          // Q (scaled)
__device__ __align__(256) __half g_K[(size_t)BB * LVIS * DD];   // K, later AO
__device__ __align__(256) __half g_V[(size_t)BB * LVIS * DD];   // V row-major
__device__ __align__(256) __half g_TGV[BB * HH * LTEXT * HD];   // TGV row-major
__device__ __align__(256) float g_M[BB * HH * LTEXT];
__device__ __align__(256) float g_L[BB * HH * LTEXT];

// ---------------- helpers --------------------------------------------------------
__device__ __forceinline__ uint32_t smem_u32(const void* p) {
    uint32_t a;
    asm("{ .reg .u64 t; cvta.to.shared.u64 t, %1; cvt.u32.u64 %0, t; }" : "=r"(a) : "l"(p));
    return a;
}
__device__ __forceinline__ void ldsm4(uint32_t* r, uint32_t addr) {
    asm volatile("ldmatrix.sync.aligned.m8n8.x4.shared.b16 {%0,%1,%2,%3}, [%4];"
                 : "=r"(r[0]), "=r"(r[1]), "=r"(r[2]), "=r"(r[3]) : "r"(addr));
}
__device__ __forceinline__ void ldsm4t(uint32_t* r, uint32_t addr) {
    asm volatile("ldmatrix.sync.aligned.m8n8.x4.trans.shared.b16 {%0,%1,%2,%3}, [%4];"
                 : "=r"(r[0]), "=r"(r[1]), "=r"(r[2]), "=r"(r[3]) : "r"(addr));
}
__device__ __forceinline__ void mma_h(float* d, const uint32_t* a, const uint32_t* b) {
    asm volatile("mma.sync.aligned.m16n8k16.row.col.f32.f16.f16.f32 "
                 "{%0,%1,%2,%3}, {%4,%5,%6,%7}, {%8,%9}, {%0,%1,%2,%3};"
                 : "+f"(d[0]), "+f"(d[1]), "+f"(d[2]), "+f"(d[3])
                 : "r"(a[0]), "r"(a[1]), "r"(a[2]), "r"(a[3]), "r"(b[0]), "r"(b[1]));
}
__device__ __forceinline__ void cp_async16(uint32_t dst, const void* src) {
    asm volatile("cp.async.cg.shared.global [%0], [%1], 16;" :: "r"(dst), "l"(src));
}
#define CP_COMMIT() asm volatile("cp.async.commit_group;" ::: "memory")
#define CP_WAIT0() asm volatile("cp.async.wait_group 0;" ::: "memory")

__device__ __forceinline__ uint32_t packh(float a, float b) {
    __half2 h = __floats2half2_rn(a, b);
    return *(uint32_t*)&h;
}

// ---------------- conversion kernels ---------------------------------------------
__global__ void convert_half(const float* __restrict__ src, int dst_sel, size_t n4)
{
    __half* dst = dst_sel ? g_A : g_T;
    size_t stride = (size_t)gridDim.x * blockDim.x;
    for (size_t i = (size_t)blockIdx.x * blockDim.x + threadIdx.x; i < n4; i += stride) {
        float4 v = ((const float4*)src)[i];
        uint2 p = {packh(v.x, v.y), packh(v.z, v.w)};
        ((uint2*)dst)[i] = p;
    }
}

// W[K,N] fp32 -> W^T[N,K] fp16
__global__ void convert_wt(const float* __restrict__ W, int widx)
{
    __shared__ float t[32][33];
    int tx = threadIdx.x, ty = threadIdx.y;   // (32,8)
    int n = blockIdx.x * 32 + tx;
    int k0 = blockIdx.y * 32;
#pragma unroll
    for (int j = 0; j < 32; j += 8)
        t[ty + j][tx] = W[(size_t)(k0 + ty + j) * DD + n];
    __syncthreads();
    __half* wt = g_W + (size_t)widx * DD * DD;
    int k = k0 + tx;
    int nn0 = blockIdx.x * 32;
#pragma unroll
    for (int j = 0; j < 32; j += 8)
        wt[(size_t)(nn0 + ty + j) * DD + k] = __float2half(t[tx][ty + j]);
}

// ---------------- fp16 GEMM on mma.sync -------------------------------------------
// C[M,1024] = alpha*(A@W^T + bias). 128x128 tile, BK=32, 8 warps (2m x 4n).
// a_sel: 0 = text, 1 = hidden, 2 = AO (g_K). c_mode: 0 = fp32 Cx, 1 = Q, 2 = K, 3 = V.
#define APAD 40
#define TILE_B (128 * APAD * 2)      // 10240 B
#define STAGE_B (2 * TILE_B)
#define G_SMEM (2 * STAGE_B)         // 40960 B

__global__ void __launch_bounds__(256)
gemm_h(int a_sel, int w_idx, const float* __restrict__ bias, float* __restrict__ Cx,
       int c_mode, float alpha)
{
    extern __shared__ __align__(256) char smem[];
    const uint32_t sb = smem_u32(smem);
    const int tid = threadIdx.x;
    const int wid = tid >> 5, lane = tid & 31;
    const int warp_m = wid & 1, warp_n = wid >> 1;

    const __half* A = (a_sel == 0) ? g_T : (a_sel == 1) ? g_A : g_K;
    const __half* B = g_W + (size_t)w_idx * DD * DD;

    const int n0 = blockIdx.x * 128;
    const size_t m0 = (size_t)blockIdx.y * 128;

    float acc[4][4][4] = {};

    auto issue = [&](int kt, int stage) {
        const int k0 = kt * 32;
        const uint32_t sdst = sb + stage * STAGE_B;
#pragma unroll
        for (int i = 0; i < 4; i++) {
            int q = tid + i * 256;
            int tile = q >> 9, rem = q & 511, r = rem >> 2, seg = rem & 3;
            const __half* src = tile ? B + (size_t)(n0 + r) * DD + k0 + seg * 8
                                     : A + (m0 + r) * DD + k0 + seg * 8;
            cp_async16(sdst + tile * TILE_B + (r * APAD + seg * 8) * 2, src);
        }
        CP_COMMIT();
    };

    issue(0, 0);
    for (int kt = 0; kt < 32; kt++) {
        if (kt + 1 < 32) {
            issue(kt + 1, (kt + 1) & 1);
            asm volatile("cp.async.wait_group 1;" ::: "memory");
        } else {
            CP_WAIT0();
        }
        __syncthreads();

        const uint32_t so = sb + (kt & 1) * STAGE_B;
        const int lm = lane & 7, quad = lane >> 3;
#pragma unroll
        for (int ks = 0; ks < 2; ks++) {
            uint32_t af[4][4], bf[2][4];
            const int arow = warp_m * 64 + (lane & 15);
            const int acol = ks * 16 + (lane >> 4) * 8;
#pragma unroll
            for (int mi = 0; mi < 4; mi++)
                ldsm4(af[mi], so + ((arow + mi * 16) * APAD + acol) * 2);
            const int brow = warp_n * 32 + ((quad & 2) ? 8 : 0) + lm;
            const int bcol = ks * 16 + (quad & 1) * 8;
#pragma unroll
            for (int np = 0; np < 2; np++)
                ldsm4(bf[np], so + TILE_B + ((brow + np * 16) * APAD + bcol) * 2);
#pragma unroll
            for (int mi = 0; mi < 4; mi++)
#pragma unroll
                for (int ni = 0; ni < 4; ni++)
                    mma_h(acc[mi][ni], af[mi], &bf[ni >> 1][(ni & 1) * 2]);
        }
        __syncthreads();
    }

    // epilogue
    __half* Ch = (c_mode == 1) ? g_Q : (c_mode == 2) ? g_K : g_V;
#pragma unroll
    for (int ni = 0; ni < 4; ni++) {
        const int col = n0 + warp_n * 32 + ni * 8 + (lane & 3) * 2;
        const float b0 = bias[col], b1 = bias[col + 1];
#pragma unroll
        for (int mi = 0; mi < 4; mi++) {
            const size_t r0 = m0 + warp_m * 64 + mi * 16 + (lane >> 2);
            float v00 = alpha * (acc[mi][ni][0] + b0);
            float v01 = alpha * (acc[mi][ni][1] + b1);
            float v10 = alpha * (acc[mi][ni][2] + b0);
            float v11 = alpha * (acc[mi][ni][3] + b1);
            if (c_mode == 0) {
                *(float2*)&Cx[r0 * DD + col] = {v00, v01};
                *(float2*)&Cx[(r0 + 8) * DD + col] = {v10, v11};
            } else {
                *(uint32_t*)&Ch[r0 * DD + col] = packh(v00, v01);
                *(uint32_t*)&Ch[(r0 + 8) * DD + col] = packh(v10, v11);
            }
        }
    }
}

// ---------------- attention pass 1 (fp16 flash) -----------------------------------
// block = 256 threads (8 warps), one (b,h). warp w owns t-rows w*16..+15.
#define AT_STRIDE 72
#define AT_TILE (128 * AT_STRIDE * 2)   // 18432 B
#define P1_SMEM (3 * AT_TILE)           // Q,K,V = 55296 B

__global__ void __launch_bounds__(256, 2)
attn1_h()
{
    extern __shared__ __align__(256) char smem[];
    const uint32_t sb = smem_u32(smem);
    const int tid = threadIdx.x;
    const int wid = tid >> 5, lane = tid & 31;
    const int bh = blockIdx.x, b = bh >> 4, h = bh & 15;

    const __half* Qg = g_Q + (size_t)(b * LTEXT) * DD + h * HD;

    // Q tile: 128 rows x 64 half = 8 segs of 16B per row -> 1024 segs
#pragma unroll
    for (int i = 0; i < 4; i++) {
        int q = tid + i * 256;
        int r = q >> 3, s = q & 7;
        cp_async16(sb + r * (AT_STRIDE * 2) + s * 16, Qg + (size_t)r * DD + s * 8);
    }

    auto issue_kv = [&](int cc) {
        const size_t row0 = (size_t)b * LVIS + cc * 128;
#pragma unroll
        for (int i = 0; i < 8; i++) {
            int q = tid + i * 256;
            int tile = q >> 10, rem = q & 1023, r = rem >> 3, s = rem & 7;
            const __half* src = tile ? g_V + (row0 + r) * DD + h * HD + s * 8
                                     : g_K + (row0 + r) * DD + h * HD + s * 8;
            cp_async16(sb + (1 + tile) * AT_TILE + r * (AT_STRIDE * 2) + s * 16, src);
        }
    };

    issue_kv(0);
    CP_COMMIT();
    CP_WAIT0();
    __syncthreads();

    // Q fragments: 4 k16 steps over d=64
    uint32_t qf[4][4];
#pragma unroll
    for (int ks = 0; ks < 4; ks++) {
        uint32_t off = ((wid * 16 + (lane & 15)) * AT_STRIDE + ks * 16 + (lane >> 4) * 8) * 2;
        ldsm4(qf[ks], sb + off);
    }

    float m0 = -1e30f, m1 = -1e30f, l0 = 0.f, l1 = 0.f;
    float O[8][4] = {};
    const int lm = lane & 7, quad = lane >> 3;

    for (int cc = 0; cc < LVIS / 128; cc++) {
        // ---- S = Q K^T (16 n8-tiles over s=128)
        float S[16][4] = {};
#pragma unroll
        for (int nb = 0; nb < 4; nb++) {
#pragma unroll
            for (int ks = 0; ks < 4; ks++) {
                uint32_t bk[2][4];
                const int brow = nb * 32 + ((quad & 2) ? 8 : 0) + lm;
                const int bcol = ks * 16 + (quad & 1) * 8;
#pragma unroll
                for (int np = 0; np < 2; np++)
                    ldsm4(bk[np], sb + AT_TILE + ((brow + np * 16) * AT_STRIDE + bcol) * 2);
#pragma unroll
                for (int ni = 0; ni < 4; ni++)
                    mma_h(S[nb * 4 + ni], qf[ks], &bk[ni >> 1][(ni & 1) * 2]);
            }
        }

        // ---- online softmax
        float mx0 = S[0][0], mx1 = S[0][2];
#pragma unroll
        for (int nt = 0; nt < 16; nt++) {
            mx0 = fmaxf(mx0, fmaxf(S[nt][0], S[nt][1]));
            mx1 = fmaxf(mx1, fmaxf(S[nt][2], S[nt][3]));
        }
        mx0 = fmaxf(mx0, __shfl_xor_sync(0xffffffffu, mx0, 1));
        mx0 = fmaxf(mx0, __shfl_xor_sync(0xffffffffu, mx0, 2));
        mx1 = fmaxf(mx1, __shfl_xor_sync(0xffffffffu, mx1, 1));
        mx1 = fmaxf(mx1, __shfl_xor_sync(0xffffffffu, mx1, 2));
        float mn0 = fmaxf(m0, mx0), mn1 = fmaxf(m1, mx1);
        float corr0 = __expf(m0 - mn0), corr1 = __expf(m1 - mn1);
        m0 = mn0; m1 = mn1;
        float rs0 = 0.f, rs1 = 0.f;
#pragma unroll
        for (int nt = 0; nt < 16; nt++) {
            S[nt][0] = __expf(S[nt][0] - m0); rs0 += S[nt][0];
            S[nt][1] = __expf(S[nt][1] - m0); rs0 += S[nt][1];
            S[nt][2] = __expf(S[nt][2] - m1); rs1 += S[nt][2];
            S[nt][3] = __expf(S[nt][3] - m1); rs1 += S[nt][3];
        }
        rs0 += __shfl_xor_sync(0xffffffffu, rs0, 1);
        rs0 += __shfl_xor_sync(0xffffffffu, rs0, 2);
        rs1 += __shfl_xor_sync(0xffffffffu, rs1, 1);
        rs1 += __shfl_xor_sync(0xffffffffu, rs1, 2);
        l0 = l0 * corr0 + rs0;
        l1 = l1 * corr1 + rs1;
#pragma unroll
        for (int nt = 0; nt < 8; nt++) {
            O[nt][0] *= corr0; O[nt][1] *= corr0;
            O[nt][2] *= corr1; O[nt][3] *= corr1;
        }

        // ---- O += P V  (P packed fp16 in A-fragment layout; V via trans ldmatrix)
#pragma unroll
        for (int ks2 = 0; ks2 < 8; ks2++) {
            uint32_t pa[4] = {packh(S[2 * ks2][0], S[2 * ks2][1]),
                              packh(S[2 * ks2][2], S[2 * ks2][3]),
                              packh(S[2 * ks2 + 1][0], S[2 * ks2 + 1][1]),
                              packh(S[2 * ks2 + 1][2], S[2 * ks2 + 1][3])};
            const int vrow = ks2 * 16 + ((lane >> 3) & 1) * 8 + (lane & 7);
#pragma unroll
            for (int nv = 0; nv < 4; nv++) {
                const int vcol = nv * 16 + (lane >> 4) * 8;
                uint32_t bv[4];
                ldsm4t(bv, sb + 2 * AT_TILE + (vrow * AT_STRIDE + vcol) * 2);
                mma_h(O[nv * 2], pa, &bv[0]);
                mma_h(O[nv * 2 + 1], pa, &bv[2]);
            }
        }

        __syncthreads();
        if (cc + 1 < LVIS / 128) {
            issue_kv(cc + 1);
            CP_COMMIT();
            CP_WAIT0();
            __syncthreads();
        }
    }

    // ---- write TGV (fp16) + stats
    const float inv0 = 1.f / l0, inv1 = 1.f / l1;
    const int r = lane >> 2, q = lane & 3;
    const int t0 = wid * 16 + r, t1 = t0 + 8;
#pragma unroll
    for (int nt = 0; nt < 8; nt++) {
        int col = nt * 8 + q * 2;
        *(uint32_t*)&g_TGV[((size_t)bh * 128 + t0) * 64 + col] =
            packh(O[nt][0] * inv0, O[nt][1] * inv0);
        *(uint32_t*)&g_TGV[((size_t)bh * 128 + t1) * 64 + col] =
            packh(O[nt][2] * inv1, O[nt][3] * inv1);
    }
    if (q == 0) {
        g_M[bh * 128 + t0] = m0; g_M[bh * 128 + t1] = m1;
        g_L[bh * 128 + t0] = l0; g_L[bh * 128 + t1] = l1;
    }
}

// ---------------- attention pass 2 (fp16) -----------------------------------------
// grid (32 s-chunks, 256 bh). AO written into g_K (fp16).
#define P2_SMEM (3 * AT_TILE + 1024)

__global__ void __launch_bounds__(256, 2)
attn2_h()
{
    extern __shared__ __align__(256) char smem[];
    const uint32_t sb = smem_u32(smem);
    float* m_s = (float*)(smem + 3 * AT_TILE);
    float* rl_s = m_s + 128;
    const int tid = threadIdx.x;
    const int wid = tid >> 5, lane = tid & 31;
    const int cc = blockIdx.x, bh = blockIdx.y, b = bh >> 4, h = bh & 15;
    const size_t row0 = (size_t)b * LVIS + cc * 128;

    // loads: Q, K-chunk, TGV -> 3 tiles x 1024 segs
#pragma unroll
    for (int i = 0; i < 12; i++) {
        int q = tid + i * 256;
        int tile = q >> 10, rem = q & 1023, r = rem >> 3, s = rem & 7;
        const __half* src;
        if (tile == 0)      src = g_Q + (size_t)(b * LTEXT + r) * DD + h * HD + s * 8;
        else if (tile == 1) src = g_K + (row0 + r) * DD + h * HD + s * 8;
        else                src = g_TGV + ((size_t)bh * 128 + r) * 64 + s * 8;
        cp_async16(sb + tile * AT_TILE + r * (AT_STRIDE * 2) + s * 16, src);
    }
    CP_COMMIT();
    if (tid < 128) {
        m_s[tid] = g_M[bh * 128 + tid];
        rl_s[tid] = 1.f / g_L[bh * 128 + tid];
    }
    CP_WAIT0();
    __syncthreads();

    // A fragments: this warp's 16 s-rows of K
    uint32_t kf[4][4];
#pragma unroll
    for (int ks = 0; ks < 4; ks++) {
        uint32_t off = ((wid * 16 + (lane & 15)) * AT_STRIDE + ks * 16 + (lane >> 4) * 8) * 2;
        ldsm4(kf[ks], sb + AT_TILE + off);
    }

    // S^T = K Q^T
    float S[16][4] = {};
    const int lm = lane & 7, quad = lane >> 3;
#pragma unroll
    for (int nb = 0; nb < 4; nb++) {
#pragma unroll
        for (int ks = 0; ks < 4; ks++) {
            uint32_t bq[2][4];
            const int brow = nb * 32 + ((quad & 2) ? 8 : 0) + lm;
            const int bcol = ks * 16 + (quad & 1) * 8;
#pragma unroll
            for (int np = 0; np < 2; np++)
                ldsm4(bq[np], sb + ((brow + np * 16) * AT_STRIDE + bcol) * 2);
#pragma unroll
            for (int ni = 0; ni < 4; ni++)
                mma_h(S[nb * 4 + ni], kf[ks], &bq[ni >> 1][(ni & 1) * 2]);
        }
    }

    // P^T[s][t] = exp(S^T - m[t]) / l[t]
    const int q = lane & 3;
#pragma unroll
    for (int nt = 0; nt < 16; nt++) {
        int c0 = nt * 8 + q * 2;
        S[nt][0] = __expf(S[nt][0] - m_s[c0]) * rl_s[c0];
        S[nt][1] = __expf(S[nt][1] - m_s[c0 + 1]) * rl_s[c0 + 1];
        S[nt][2] = __expf(S[nt][2] - m_s[c0]) * rl_s[c0];
        S[nt][3] = __expf(S[nt][3] - m_s[c0 + 1]) * rl_s[c0 + 1];
    }

    // O = P^T TGV
    float O[8][4] = {};
#pragma unroll
    for (int ks2 = 0; ks2 < 8; ks2++) {
        uint32_t pa[4] = {packh(S[2 * ks2][0], S[2 * ks2][1]),
                          packh(S[2 * ks2][2], S[2 * ks2][3]),
                          packh(S[2 * ks2 + 1][0], S[2 * ks2 + 1][1]),
                          packh(S[2 * ks2 + 1][2], S[2 * ks2 + 1][3])};
        const int vrow = ks2 * 16 + ((lane >> 3) & 1) * 8 + (lane & 7);
#pragma unroll
        for (int nv = 0; nv < 4; nv++) {
            const int vcol = nv * 16 + (lane >> 4) * 8;
            uint32_t bv[4];
            ldsm4t(bv, sb + 2 * AT_TILE + (vrow * AT_STRIDE + vcol) * 2);
            mma_h(O[nv * 2], pa, &bv[0]);
            mma_h(O[nv * 2 + 1], pa, &bv[2]);
        }
    }

    // write AO (fp16) into g_K — unique owner of these rows x cols [h*64..+63]
    const int r = lane >> 2;
    const size_t s0r = row0 + wid * 16 + r;
#pragma unroll
    for (int nt = 0; nt < 8; nt++) {
        int col = h * HD + nt * 8 + q * 2;
        *(uint32_t*)&g_K[s0r * DD + col] = packh(O[nt][0], O[nt][1]);
        *(uint32_t*)&g_K[(s0r + 8) * DD + col] = packh(O[nt][2], O[nt][3]);
    }
}

// ---------------- launch ----------------------------------------------------------
extern "C" void kernel_launch(void* const* d_in, const int* in_sizes, int n_in,
                              void* d_out, int out_size)
{
    const float* hidden = nullptr;
    const float* text = nullptr;
    const float* Ws[4] = {nullptr, nullptr, nullptr, nullptr};
    const float* bs[4] = {nullptr, nullptr, nullptr, nullptr};
    int nw = 0, nb = 0;
    for (int i = 0; i < n_in; i++) {
        int sz = in_sizes[i];
        const float* p = (const float*)d_in[i];
        if (sz == BB * LVIS * DD) { if (!hidden) hidden = p; }
        else if (sz == LTEXT * BB * DD) { if (!text) text = p; }
        else if (sz == DD * DD) { if (nw < 4) Ws[nw++] = p; }
        else if (sz == DD) { if (nb < 4) bs[nb++] = p; }
    }
    if (!hidden) hidden = (const float*)d_in[0];
    if (!text) text = (const float*)d_in[1];
    if (nw < 4) { Ws[0]=(const float*)d_in[2]; Ws[1]=(const float*)d_in[4];
                  Ws[2]=(const float*)d_in[6]; Ws[3]=(const float*)d_in[8]; }
    if (nb < 4) { bs[0]=(const float*)d_in[3]; bs[1]=(const float*)d_in[5];
                  bs[2]=(const float*)d_in[7]; bs[3]=(const float*)d_in[9]; }
    float* out = (float*)d_out;

    cudaFuncSetAttribute(gemm_h, cudaFuncAttributeMaxDynamicSharedMemorySize, G_SMEM);
    cudaFuncSetAttribute(attn1_h, cudaFuncAttributeMaxDynamicSharedMemorySize, P1_SMEM);
    cudaFuncSetAttribute(attn2_h, cudaFuncAttributeMaxDynamicSharedMemorySize, P2_SMEM);

    for (int w = 0; w < 4; w++)
        convert_wt<<<dim3(32, 32), dim3(32, 8)>>>(Ws[w], w);
    convert_half<<<2048, 256>>>(text, 0, (size_t)LTEXT * BB * DD / 4);
    convert_half<<<8192, 256>>>(hidden, 1, (size_t)BB * LVIS * DD / 4);

    gemm_h<<<dim3(8, 16), 256, G_SMEM>>>(0, 0, bs[0], nullptr, 1, 0.125f);   // Q
    gemm_h<<<dim3(8, 512), 256, G_SMEM>>>(1, 1, bs[1], nullptr, 2, 1.f);     // K
    gemm_h<<<dim3(8, 512), 256, G_SMEM>>>(1, 2, bs[2], nullptr, 3, 1.f);     // V

    attn1_h<<<BB * HH, 256, P1_SMEM>>>();
    attn2_h<<<dim3(LVIS / 128, BB * HH), 256, P2_SMEM>>>();

    gemm_h<<<dim3(8, 512), 256, G_SMEM>>>(2, 3, bs[3], out, 0, 1.f);         // O
}

// round 13
// speedup vs baseline: 5.1319x; 1.0226x over previous
#include <cuda_runtime.h>
#include <cuda_fp16.h>
#include <cstdint>
#include <cstddef>

#define BB 16
#define LTEXT 128
#define LVIS 4096
#define DD 1024
#define HH 16
#define HD 64

// ---------------- scratch (fp16 interchange) --------------------------------------
__device__ __align__(256) __half g_A[(size_t)BB * LVIS * DD];   // hidden fp16 134MB
__device__ __align__(256) __half g_T[BB * LTEXT * DD];          // text fp16 4MB
__device__ __align__(256) __half g_W[4 * DD * DD];              // W^T (N,K) fp16 8MB
__device__ __align__(256) __half g_Q[BB * LTEXT * DD];          // Q (scaled)
__device__ __align__(256) __half g_K[(size_t)BB * LVIS * DD];   // K, later AO
__device__ __align__(256) __half g_V[(size_t)BB * LVIS * DD];   // V row-major
__device__ __align__(256) __half g_TGV[BB * HH * LTEXT * HD];   // TGV row-major
__device__ __align__(256) float g_M[BB * HH * LTEXT];
__device__ __align__(256) float g_L[BB * HH * LTEXT];

// ---------------- helpers --------------------------------------------------------
__device__ __forceinline__ uint32_t smem_u32(const void* p) {
    uint32_t a;
    asm("{ .reg .u64 t; cvta.to.shared.u64 t, %1; cvt.u32.u64 %0, t; }" : "=r"(a) : "l"(p));
    return a;
}
__device__ __forceinline__ void ldsm4(uint32_t* r, uint32_t addr) {
    asm volatile("ldmatrix.sync.aligned.m8n8.x4.shared.b16 {%0,%1,%2,%3}, [%4];"
                 : "=r"(r[0]), "=r"(r[1]), "=r"(r[2]), "=r"(r[3]) : "r"(addr));
}
__device__ __forceinline__ void ldsm4t(uint32_t* r, uint32_t addr) {
    asm volatile("ldmatrix.sync.aligned.m8n8.x4.trans.shared.b16 {%0,%1,%2,%3}, [%4];"
                 : "=r"(r[0]), "=r"(r[1]), "=r"(r[2]), "=r"(r[3]) : "r"(addr));
}
__device__ __forceinline__ void mma_h(float* d, const uint32_t* a, const uint32_t* b) {
    asm volatile("mma.sync.aligned.m16n8k16.row.col.f32.f16.f16.f32 "
                 "{%0,%1,%2,%3}, {%4,%5,%6,%7}, {%8,%9}, {%0,%1,%2,%3};"
                 : "+f"(d[0]), "+f"(d[1]), "+f"(d[2]), "+f"(d[3])
                 : "r"(a[0]), "r"(a[1]), "r"(a[2]), "r"(a[3]), "r"(b[0]), "r"(b[1]));
}
__device__ __forceinline__ void cp_async16(uint32_t dst, const void* src) {
    asm volatile("cp.async.cg.shared.global [%0], [%1], 16;" :: "r"(dst), "l"(src));
}
#define CP_COMMIT() asm volatile("cp.async.commit_group;" ::: "memory")
#define CP_WAIT0() asm volatile("cp.async.wait_group 0;" ::: "memory")
#define CP_WAIT1() asm volatile("cp.async.wait_group 1;" ::: "memory")
#define CP_WAIT2() asm volatile("cp.async.wait_group 2;" ::: "memory")

__device__ __forceinline__ uint32_t packh(float a, float b) {
    __half2 h = __floats2half2_rn(a, b);
    return *(uint32_t*)&h;
}

// ---------------- conversion kernels ---------------------------------------------
__global__ void convert_half(const float* __restrict__ src, int dst_sel, size_t n4)
{
    __half* dst = dst_sel ? g_A : g_T;
    size_t stride = (size_t)gridDim.x * blockDim.x;
    for (size_t i = (size_t)blockIdx.x * blockDim.x + threadIdx.x; i < n4; i += stride) {
        float4 v = ((const float4*)src)[i];
        uint2 p = {packh(v.x, v.y), packh(v.z, v.w)};
        ((uint2*)dst)[i] = p;
    }
}

// W[K,N] fp32 -> W^T[N,K] fp16
__global__ void convert_wt(const float* __restrict__ W, int widx)
{
    __shared__ float t[32][33];
    int tx = threadIdx.x, ty = threadIdx.y;   // (32,8)
    int n = blockIdx.x * 32 + tx;
    int k0 = blockIdx.y * 32;
#pragma unroll
    for (int j = 0; j < 32; j += 8)
        t[ty + j][tx] = W[(size_t)(k0 + ty + j) * DD + n];
    __syncthreads();
    __half* wt = g_W + (size_t)widx * DD * DD;
    int k = k0 + tx;
    int nn0 = blockIdx.x * 32;
#pragma unroll
    for (int j = 0; j < 32; j += 8)
        wt[(size_t)(nn0 + ty + j) * DD + k] = __float2half(t[tx][ty + j]);
}

// ---------------- fp16 GEMM, 4-stage cp.async pipeline ----------------------------
// C[M,1024] = alpha*(A@W^T + bias). 128x128 tile, BK=32, 8 warps (2m x 4n).
// a_sel: 0 = text, 1 = hidden, 2 = AO (g_K). c_mode: 0 = fp32 Cx, 1 = Q, 2 = K, 3 = V.
#define APAD 40
#define TILE_B (128 * APAD * 2)      // 10240 B (one operand tile)
#define STAGE_B (2 * TILE_B)         // 20480 B (A+B)
#define G_STAGES 4
#define G_SMEM (G_STAGES * STAGE_B)  // 81920 B

__global__ void __launch_bounds__(256)
gemm_h(int a_sel, int w_idx, const float* __restrict__ bias, float* __restrict__ Cx,
       int c_mode, float alpha)
{
    extern __shared__ __align__(256) char smem[];
    const uint32_t sb = smem_u32(smem);
    const int tid = threadIdx.x;
    const int wid = tid >> 5, lane = tid & 31;
    const int warp_m = wid & 1, warp_n = wid >> 1;

    const __half* A = (a_sel == 0) ? g_T : (a_sel == 1) ? g_A : g_K;
    const __half* B = g_W + (size_t)w_idx * DD * DD;

    const int n0 = blockIdx.x * 128;
    const size_t m0 = (size_t)blockIdx.y * 128;

    float acc[4][4][4] = {};

    auto issue = [&](int kt) {
        const int k0 = kt * 32;
        const uint32_t sdst = sb + (kt & 3) * STAGE_B;
#pragma unroll
        for (int i = 0; i < 4; i++) {
            int q = tid + i * 256;
            int tile = q >> 9, rem = q & 511, r = rem >> 2, seg = rem & 3;
            const __half* src = tile ? B + (size_t)(n0 + r) * DD + k0 + seg * 8
                                     : A + (m0 + r) * DD + k0 + seg * 8;
            cp_async16(sdst + tile * TILE_B + (r * APAD + seg * 8) * 2, src);
        }
        CP_COMMIT();
    };

    issue(0); issue(1); issue(2);
    for (int kt = 0; kt < 32; kt++) {
        if (kt < 30) CP_WAIT2();
        else if (kt == 30) CP_WAIT1();
        else CP_WAIT0();
        __syncthreads();
        // refill stage (kt+3)&3 == (kt-1)&3 — consumed at iter kt-1, all warps
        // passed the sync above after finishing it.
        if (kt + 3 < 32) issue(kt + 3);

        const uint32_t so = sb + (kt & 3) * STAGE_B;
        const int lm = lane & 7, quad = lane >> 3;
#pragma unroll
        for (int ks = 0; ks < 2; ks++) {
            uint32_t af[4][4], bf[2][4];
            const int arow = warp_m * 64 + (lane & 15);
            const int acol = ks * 16 + (lane >> 4) * 8;
#pragma unroll
            for (int mi = 0; mi < 4; mi++)
                ldsm4(af[mi], so + ((arow + mi * 16) * APAD + acol) * 2);
            const int brow = warp_n * 32 + ((quad & 2) ? 8 : 0) + lm;
            const int bcol = ks * 16 + (quad & 1) * 8;
#pragma unroll
            for (int np = 0; np < 2; np++)
                ldsm4(bf[np], so + TILE_B + ((brow + np * 16) * APAD + bcol) * 2);
#pragma unroll
            for (int mi = 0; mi < 4; mi++)
#pragma unroll
                for (int ni = 0; ni < 4; ni++)
                    mma_h(acc[mi][ni], af[mi], &bf[ni >> 1][(ni & 1) * 2]);
        }
    }

    // epilogue
    __half* Ch = (c_mode == 1) ? g_Q : (c_mode == 2) ? g_K : g_V;
#pragma unroll
    for (int ni = 0; ni < 4; ni++) {
        const int col = n0 + warp_n * 32 + ni * 8 + (lane & 3) * 2;
        const float b0 = bias[col], b1 = bias[col + 1];
#pragma unroll
        for (int mi = 0; mi < 4; mi++) {
            const size_t r0 = m0 + warp_m * 64 + mi * 16 + (lane >> 2);
            float v00 = alpha * (acc[mi][ni][0] + b0);
            float v01 = alpha * (acc[mi][ni][1] + b1);
            float v10 = alpha * (acc[mi][ni][2] + b0);
            float v11 = alpha * (acc[mi][ni][3] + b1);
            if (c_mode == 0) {
                *(float2*)&Cx[r0 * DD + col] = {v00, v01};
                *(float2*)&Cx[(r0 + 8) * DD + col] = {v10, v11};
            } else {
                *(uint32_t*)&Ch[r0 * DD + col] = packh(v00, v01);
                *(uint32_t*)&Ch[(r0 + 8) * DD + col] = packh(v10, v11);
            }
        }
    }
}

// ---------------- attention pass 1 (fp16 flash, double-buffered KV) ---------------
// block = 256 threads (8 warps), one (b,h). warp w owns t-rows w*16..+15.
#define AT_STRIDE 72
#define AT_TILE (128 * AT_STRIDE * 2)   // 18432 B
#define KV_SET (2 * AT_TILE)            // K+V set
#define P1_SMEM (AT_TILE + 2 * KV_SET)  // Q + 2 KV sets = 92160 B

__global__ void __launch_bounds__(256, 2)
attn1_h()
{
    extern __shared__ __align__(256) char smem[];
    const uint32_t sb = smem_u32(smem);
    const int tid = threadIdx.x;
    const int wid = tid >> 5, lane = tid & 31;
    const int bh = blockIdx.x, b = bh >> 4, h = bh & 15;

    const __half* Qg = g_Q + (size_t)(b * LTEXT) * DD + h * HD;

    // Q tile: 128 rows x 64 half = 8 segs of 16B per row -> 1024 segs
#pragma unroll
    for (int i = 0; i < 4; i++) {
        int q = tid + i * 256;
        int r = q >> 3, s = q & 7;
        cp_async16(sb + r * (AT_STRIDE * 2) + s * 16, Qg + (size_t)r * DD + s * 8);
    }

    auto issue_kv = [&](int cc) {
        const size_t row0 = (size_t)b * LVIS + cc * 128;
        const uint32_t base = sb + AT_TILE + (cc & 1) * KV_SET;
#pragma unroll
        for (int i = 0; i < 8; i++) {
            int q = tid + i * 256;
            int tile = q >> 10, rem = q & 1023, r = rem >> 3, s = rem & 7;
            const __half* src = tile ? g_V + (row0 + r) * DD + h * HD + s * 8
                                     : g_K + (row0 + r) * DD + h * HD + s * 8;
            cp_async16(base + tile * AT_TILE + r * (AT_STRIDE * 2) + s * 16, src);
        }
    };

    issue_kv(0);
    CP_COMMIT();            // G0: Q + KV0
    CP_WAIT0();
    __syncthreads();

    // Q fragments: 4 k16 steps over d=64
    uint32_t qf[4][4];
#pragma unroll
    for (int ks = 0; ks < 4; ks++) {
        uint32_t off = ((wid * 16 + (lane & 15)) * AT_STRIDE + ks * 16 + (lane >> 4) * 8) * 2;
        ldsm4(qf[ks], sb + off);
    }

    issue_kv(1);
    CP_COMMIT();            // G1: KV1 (in flight during chunk 0 compute)

    float m0 = -1e30f, m1 = -1e30f, l0 = 0.f, l1 = 0.f;
    float O[8][4] = {};
    const int lm = lane & 7, quad = lane >> 3;

    for (int cc = 0; cc < LVIS / 128; cc++) {
        if (cc > 0) {
            if (cc < 31) CP_WAIT1(); else CP_WAIT0();
            __syncthreads();   // publish KV set (cc&1); also: all warps done with prev use
        }
        const uint32_t kvb = sb + AT_TILE + (cc & 1) * KV_SET;

        // ---- S = Q K^T (16 n8-tiles over s=128)
        float S[16][4] = {};
#pragma unroll
        for (int nb = 0; nb < 4; nb++) {
#pragma unroll
            for (int ks = 0; ks < 4; ks++) {
                uint32_t bk[2][4];
                const int brow = nb * 32 + ((quad & 2) ? 8 : 0) + lm;
                const int bcol = ks * 16 + (quad & 1) * 8;
#pragma unroll
                for (int np = 0; np < 2; np++)
                    ldsm4(bk[np], kvb + ((brow + np * 16) * AT_STRIDE + bcol) * 2);
#pragma unroll
                for (int ni = 0; ni < 4; ni++)
                    mma_h(S[nb * 4 + ni], qf[ks], &bk[ni >> 1][(ni & 1) * 2]);
            }
        }

        // ---- online softmax
        float mx0 = S[0][0], mx1 = S[0][2];
#pragma unroll
        for (int nt = 0; nt < 16; nt++) {
            mx0 = fmaxf(mx0, fmaxf(S[nt][0], S[nt][1]));
            mx1 = fmaxf(mx1, fmaxf(S[nt][2], S[nt][3]));
        }
        mx0 = fmaxf(mx0, __shfl_xor_sync(0xffffffffu, mx0, 1));
        mx0 = fmaxf(mx0, __shfl_xor_sync(0xffffffffu, mx0, 2));
        mx1 = fmaxf(mx1, __shfl_xor_sync(0xffffffffu, mx1, 1));
        mx1 = fmaxf(mx1, __shfl_xor_sync(0xffffffffu, mx1, 2));
        float mn0 = fmaxf(m0, mx0), mn1 = fmaxf(m1, mx1);
        float corr0 = __expf(m0 - mn0), corr1 = __expf(m1 - mn1);
        m0 = mn0; m1 = mn1;
        float rs0 = 0.f, rs1 = 0.f;
#pragma unroll
        for (int nt = 0; nt < 16; nt++) {
            S[nt][0] = __expf(S[nt][0] - m0); rs0 += S[nt][0];
            S[nt][1] = __expf(S[nt][1] - m0); rs0 += S[nt][1];
            S[nt][2] = __expf(S[nt][2] - m1); rs1 += S[nt][2];
            S[nt][3] = __expf(S[nt][3] - m1); rs1 += S[nt][3];
        }
        rs0 += __shfl_xor_sync(0xffffffffu, rs0, 1);
        rs0 += __shfl_xor_sync(0xffffffffu, rs0, 2);
        rs1 += __shfl_xor_sync(0xffffffffu, rs1, 1);
        rs1 += __shfl_xor_sync(0xffffffffu, rs1, 2);
        l0 = l0 * corr0 + rs0;
        l1 = l1 * corr1 + rs1;
#pragma unroll
        for (int nt = 0; nt < 8; nt++) {
            O[nt][0] *= corr0; O[nt][1] *= corr0;
            O[nt][2] *= corr1; O[nt][3] *= corr1;
        }

        // ---- O += P V  (P packed fp16 in A-fragment layout; V via trans ldmatrix)
#pragma unroll
        for (int ks2 = 0; ks2 < 8; ks2++) {
            uint32_t pa[4] = {packh(S[2 * ks2][0], S[2 * ks2][1]),
                              packh(S[2 * ks2][2], S[2 * ks2][3]),
                              packh(S[2 * ks2 + 1][0], S[2 * ks2 + 1][1]),
                              packh(S[2 * ks2 + 1][2], S[2 * ks2 + 1][3])};
            const int vrow = ks2 * 16 + ((lane >> 3) & 1) * 8 + (lane & 7);
#pragma unroll
            for (int nv = 0; nv < 4; nv++) {
                const int vcol = nv * 16 + (lane >> 4) * 8;
                uint32_t bv[4];
                ldsm4t(bv, kvb + AT_TILE + (vrow * AT_STRIDE + vcol) * 2);
                mma_h(O[nv * 2], pa, &bv[0]);
                mma_h(O[nv * 2 + 1], pa, &bv[2]);
            }
        }

        // refill the buffer just consumed with chunk cc+2 (all warps must be done)
        if (cc + 2 < LVIS / 128) {
            __syncthreads();
            issue_kv(cc + 2);
            CP_COMMIT();
        }
    }

    // ---- write TGV (fp16) + stats
    const float inv0 = 1.f / l0, inv1 = 1.f / l1;
    const int r = lane >> 2, q = lane & 3;
    const int t0 = wid * 16 + r, t1 = t0 + 8;
#pragma unroll
    for (int nt = 0; nt < 8; nt++) {
        int col = nt * 8 + q * 2;
        *(uint32_t*)&g_TGV[((size_t)bh * 128 + t0) * 64 + col] =
            packh(O[nt][0] * inv0, O[nt][1] * inv0);
        *(uint32_t*)&g_TGV[((size_t)bh * 128 + t1) * 64 + col] =
            packh(O[nt][2] * inv1, O[nt][3] * inv1);
    }
    if (q == 0) {
        g_M[bh * 128 + t0] = m0; g_M[bh * 128 + t1] = m1;
        g_L[bh * 128 + t0] = l0; g_L[bh * 128 + t1] = l1;
    }
}

// ---------------- attention pass 2 (fp16) -----------------------------------------
// grid (32 s-chunks, 256 bh). AO written into g_K (fp16).
#define P2_SMEM (3 * AT_TILE + 1024)

__global__ void __launch_bounds__(256, 2)
attn2_h()
{
    extern __shared__ __align__(256) char smem[];
    const uint32_t sb = smem_u32(smem);
    float* m_s = (float*)(smem + 3 * AT_TILE);
    float* rl_s = m_s + 128;
    const int tid = threadIdx.x;
    const int wid = tid >> 5, lane = tid & 31;
    const int cc = blockIdx.x, bh = blockIdx.y, b = bh >> 4, h = bh & 15;
    const size_t row0 = (size_t)b * LVIS + cc * 128;

    // loads: Q, K-chunk, TGV -> 3 tiles x 1024 segs
#pragma unroll
    for (int i = 0; i < 12; i++) {
        int q = tid + i * 256;
        int tile = q >> 10, rem = q & 1023, r = rem >> 3, s = rem & 7;
        const __half* src;
        if (tile == 0)      src = g_Q + (size_t)(b * LTEXT + r) * DD + h * HD + s * 8;
        else if (tile == 1) src = g_K + (row0 + r) * DD + h * HD + s * 8;
        else                src = g_TGV + ((size_t)bh * 128 + r) * 64 + s * 8;
        cp_async16(sb + tile * AT_TILE + r * (AT_STRIDE * 2) + s * 16, src);
    }
    CP_COMMIT();
    if (tid < 128) {
        m_s[tid] = g_M[bh * 128 + tid];
        rl_s[tid] = 1.f / g_L[bh * 128 + tid];
    }
    CP_WAIT0();
    __syncthreads();

    // A fragments: this warp's 16 s-rows of K
    uint32_t kf[4][4];
#pragma unroll
    for (int ks = 0; ks < 4; ks++) {
        uint32_t off = ((wid * 16 + (lane & 15)) * AT_STRIDE + ks * 16 + (lane >> 4) * 8) * 2;
        ldsm4(kf[ks], sb + AT_TILE + off);
    }

    // S^T = K Q^T
    float S[16][4] = {};
    const int lm = lane & 7, quad = lane >> 3;
#pragma unroll
    for (int nb = 0; nb < 4; nb++) {
#pragma unroll
        for (int ks = 0; ks < 4; ks++) {
            uint32_t bq[2][4];
            const int brow = nb * 32 + ((quad & 2) ? 8 : 0) + lm;
            const int bcol = ks * 16 + (quad & 1) * 8;
#pragma unroll
            for (int np = 0; np < 2; np++)
                ldsm4(bq[np], sb + ((brow + np * 16) * AT_STRIDE + bcol) * 2);
#pragma unroll
            for (int ni = 0; ni < 4; ni++)
                mma_h(S[nb * 4 + ni], kf[ks], &bq[ni >> 1][(ni & 1) * 2]);
        }
    }

    // P^T[s][t] = exp(S^T - m[t]) / l[t]
    const int q = lane & 3;
#pragma unroll
    for (int nt = 0; nt < 16; nt++) {
        int c0 = nt * 8 + q * 2;
        S[nt][0] = __expf(S[nt][0] - m_s[c0]) * rl_s[c0];
        S[nt][1] = __expf(S[nt][1] - m_s[c0 + 1]) * rl_s[c0 + 1];
        S[nt][2] = __expf(S[nt][2] - m_s[c0]) * rl_s[c0];
        S[nt][3] = __expf(S[nt][3] - m_s[c0 + 1]) * rl_s[c0 + 1];
    }

    // O = P^T TGV
    float O[8][4] = {};
#pragma unroll
    for (int ks2 = 0; ks2 < 8; ks2++) {
        uint32_t pa[4] = {packh(S[2 * ks2][0], S[2 * ks2][1]),
                          packh(S[2 * ks2][2], S[2 * ks2][3]),
                          packh(S[2 * ks2 + 1][0], S[2 * ks2 + 1][1]),
                          packh(S[2 * ks2 + 1][2], S[2 * ks2 + 1][3])};
        const int vrow = ks2 * 16 + ((lane >> 3) & 1) * 8 + (lane & 7);
#pragma unroll
        for (int nv = 0; nv < 4; nv++) {
            const int vcol = nv * 16 + (lane >> 4) * 8;
            uint32_t bv[4];
            ldsm4t(bv, sb + 2 * AT_TILE + (vrow * AT_STRIDE + vcol) * 2);
            mma_h(O[nv * 2], pa, &bv[0]);
            mma_h(O[nv * 2 + 1], pa, &bv[2]);
        }
    }

    // write AO (fp16) into g_K — unique owner of these rows x cols [h*64..+63]
    const int r = lane >> 2;
    const size_t s0r = row0 + wid * 16 + r;
#pragma unroll
    for (int nt = 0; nt < 8; nt++) {
        int col = h * HD + nt * 8 + q * 2;
        *(uint32_t*)&g_K[s0r * DD + col] = packh(O[nt][0], O[nt][1]);
        *(uint32_t*)&g_K[(s0r + 8) * DD + col] = packh(O[nt][2], O[nt][3]);
    }
}

// ---------------- launch ----------------------------------------------------------
extern "C" void kernel_launch(void* const* d_in, const int* in_sizes, int n_in,
                              void* d_out, int out_size)
{
    const float* hidden = nullptr;
    const float* text = nullptr;
    const float* Ws[4] = {nullptr, nullptr, nullptr, nullptr};
    const float* bs[4] = {nullptr, nullptr, nullptr, nullptr};
    int nw = 0, nb = 0;
    for (int i = 0; i < n_in; i++) {
        int sz = in_sizes[i];
        const float* p = (const float*)d_in[i];
        if (sz == BB * LVIS * DD) { if (!hidden) hidden = p; }
        else if (sz == LTEXT * BB * DD) { if (!text) text = p; }
        else if (sz == DD * DD) { if (nw < 4) Ws[nw++] = p; }
        else if (sz == DD) { if (nb < 4) bs[nb++] = p; }
    }
    if (!hidden) hidden = (const float*)d_in[0];
    if (!text) text = (const float*)d_in[1];
    if (nw < 4) { Ws[0]=(const float*)d_in[2]; Ws[1]=(const float*)d_in[4];
                  Ws[2]=(const float*)d_in[6]; Ws[3]=(const float*)d_in[8]; }
    if (nb < 4) { bs[0]=(const float*)d_in[3]; bs[1]=(const float*)d_in[5];
                  bs[2]=(const float*)d_in[7]; bs[3]=(const float*)d_in[9]; }
    float* out = (float*)d_out;

    cudaFuncSetAttribute(gemm_h, cudaFuncAttributeMaxDynamicSharedMemorySize, G_SMEM);
    cudaFuncSetAttribute(attn1_h, cudaFuncAttributeMaxDynamicSharedMemorySize, P1_SMEM);
    cudaFuncSetAttribute(attn2_h, cudaFuncAttributeMaxDynamicSharedMemorySize, P2_SMEM);

    for (int w = 0; w < 4; w++)
        convert_wt<<<dim3(32, 32), dim3(32, 8)>>>(Ws[w], w);
    convert_half<<<2048, 256>>>(text, 0, (size_t)LTEXT * BB * DD / 4);
    convert_half<<<8192, 256>>>(hidden, 1, (size_t)BB * LVIS * DD / 4);

    gemm_h<<<dim3(8, 16), 256, G_SMEM>>>(0, 0, bs[0], nullptr, 1, 0.125f);   // Q
    gemm_h<<<dim3(8, 512), 256, G_SMEM>>>(1, 1, bs[1], nullptr, 2, 1.f);     // K
    gemm_h<<<dim3(8, 512), 256, G_SMEM>>>(1, 2, bs[2], nullptr, 3, 1.f);     // V

    attn1_h<<<BB * HH, 256, P1_SMEM>>>();
    attn2_h<<<dim3(LVIS / 128, BB * HH), 256, P2_SMEM>>>();

    gemm_h<<<dim3(8, 512), 256, G_SMEM>>>(2, 3, bs[3], out, 0, 1.f);         // O
}